// round 11
// baseline (speedup 1.0000x reference)
#include <cuda_runtime.h>
#include <cuda_bf16.h>
#include <cstdint>

#define B_    4
#define C_    256
#define H_    128
#define W_    128
#define HW_   (H_*W_)
#define COMP_ 64
#define KK_   25
#define HO_   64
#define WO_   64

// Scratch (device globals; allocation is forbidden)
__device__ float g_comp[B_*HW_*COMP_];     // [b][px][ch] channel-minor
__device__ float g_mask[B_*KK_*HO_*WO_];   // NORMALIZED softmax weights
__device__ __align__(16) unsigned char g_w1b[COMP_*C_*2];

__device__ __forceinline__ uint32_t smem_u32(const void* p) {
    uint32_t a;
    asm("{ .reg .u64 t; cvta.to.shared.u64 t, %1; cvt.u32.u64 %0, t; }" : "=r"(a) : "l"(p));
    return a;
}
// ---- packed f32x2 helpers (validated on this harness in R1) ----
__device__ __forceinline__ unsigned long long pack2(float lo, float hi) {
    unsigned long long r;
    asm("mov.b64 %0, {%1, %2};" : "=l"(r)
        : "r"(__float_as_uint(lo)), "r"(__float_as_uint(hi)));
    return r;
}
__device__ __forceinline__ unsigned long long dup2(float w) {
    unsigned long long r;
    asm("mov.b64 %0, {%1, %1};" : "=l"(r) : "r"(__float_as_uint(w)));
    return r;
}
__device__ __forceinline__ void fma2(unsigned long long& d,
                                     unsigned long long a, unsigned long long b) {
    asm("fma.rn.f32x2 %0, %1, %2, %0;" : "+l"(d) : "l"(a), "l"(b));
}
__device__ __forceinline__ float2 unpack2(unsigned long long v) {
    unsigned lo, hi;
    asm("mov.b64 {%0, %1}, %2;" : "=r"(lo), "=r"(hi) : "l"(v));
    return make_float2(__uint_as_float(lo), __uint_as_float(hi));
}

// ================= Kernel P: w1 fp32 -> bf16 =================
__global__ void k_prep(const float* __restrict__ w1) {
    int idx = blockIdx.x * 256 + threadIdx.x;
    if (idx < COMP_ * C_)
        ((__nv_bfloat16*)g_w1b)[idx] = __float2bfloat16(w1[idx]);
}

// ================= Kernel A: 1x1 conv, single-phase mma.sync bf16 =================
// grid (256, 4), block 128 (4 warps x 16 px). xs holds full K=256 (32KB),
// ws 32KB, one sync, then 16 uninterrupted MMA k-steps.
#define XS_OFF   0
#define WS_OFF   32768
#define BIAS_OFF 65536
#define A_SMEM_BYTES (65536 + 256)

__global__ __launch_bounds__(128) void k_conv1(const float* __restrict__ x,
                                               const float* __restrict__ b1) {
    extern __shared__ __align__(16) char sm[];
    const uint32_t smb = smem_u32(sm);
    const int tid  = threadIdx.x;
    const int warp = tid >> 5;
    const int lane = tid & 31;
    const int b    = blockIdx.y;
    const int px0  = blockIdx.x * 64;

    // ws: rows n (64) x 256k bf16, 16B chunk cx at n*512 + ((cx^(n&7))<<4)
    {
        const uint4* wsrc = (const uint4*)g_w1b;
#pragma unroll
        for (int l = 0; l < 16; l++) {
            int i = l*128 + tid;
            int n = i >> 5, cx = i & 31;
            *(uint4*)(sm + WS_OFF + n*512 + (uint32_t)((cx ^ (n & 7)) << 4)) = wsrc[i];
        }
        if (tid < 64) ((float*)(sm + BIAS_OFF))[tid] = b1[tid];
    }

    // xs: rows ch (256) x 64px bf16 (128B rows), batched loads (MLP 8)
    {
        const float4* xsrc = (const float4*)(x + ((size_t)b * C_) * HW_ + px0);
#pragma unroll 1
        for (int g = 0; g < 4; g++) {
            float4 v[8];
#pragma unroll
            for (int j = 0; j < 8; j++) {
                int id = (g*8 + j)*128 + tid;
                int ch = id >> 4, f4 = id & 15;
                v[j] = xsrc[(size_t)ch * (HW_/4) + f4];
            }
#pragma unroll
            for (int j = 0; j < 8; j++) {
                int id = (g*8 + j)*128 + tid;
                int ch = id >> 4, f4 = id & 15;
                __nv_bfloat162 h0 = __float22bfloat162_rn(make_float2(v[j].x, v[j].y));
                __nv_bfloat162 h1 = __float22bfloat162_rn(make_float2(v[j].z, v[j].w));
                int cx = f4 >> 1;
                uint32_t off = XS_OFF + ch*128 + (uint32_t)((cx ^ (ch & 7)) << 4) + (f4 & 1) * 8;
                *(uint2*)(sm + off) = make_uint2(*(uint32_t*)&h0, *(uint32_t*)&h1);
            }
        }
    }
    __syncthreads();

    float acc[8][4];
#pragma unroll
    for (int nt = 0; nt < 8; nt++)
#pragma unroll
        for (int i = 0; i < 4; i++) acc[nt][i] = 0.f;

    const int lj  = lane & 7;
    const int lg2 = (lane >> 3) & 1;
    const int lg4 = lane >> 4;
    const int g_  = lane >> 2;
    const int tig = lane & 3;
    const int pxcol = warp*16 + lg2*8;

#pragma unroll
    for (int s = 0; s < 16; s++) {
        uint32_t a[4];
        const int krow = s*16 + lj + lg4*8;
        uint32_t addr = smb + XS_OFF + krow*128
                      + (uint32_t)(((pxcol >> 3) ^ (krow & 7)) << 4);
        asm volatile("ldmatrix.sync.aligned.m8n8.x4.trans.shared.b16 "
                     "{%0,%1,%2,%3}, [%4];"
                     : "=r"(a[0]), "=r"(a[1]), "=r"(a[2]), "=r"(a[3])
                     : "r"(addr));
        const int cx0 = 2*s;
#pragma unroll
        for (int nt = 0; nt < 8; nt++) {
            int n = nt*8 + g_;
            uint32_t ab0 = smb + WS_OFF + n*512
                         + (uint32_t)(((cx0     ) ^ (n & 7)) << 4) + tig*4;
            uint32_t ab1 = smb + WS_OFF + n*512
                         + (uint32_t)(((cx0 + 1) ^ (n & 7)) << 4) + tig*4;
            uint32_t b0, b1v;
            asm volatile("ld.shared.b32 %0, [%1];" : "=r"(b0)  : "r"(ab0));
            asm volatile("ld.shared.b32 %0, [%1];" : "=r"(b1v) : "r"(ab1));
            asm volatile(
                "mma.sync.aligned.m16n8k16.row.col.f32.bf16.bf16.f32 "
                "{%0,%1,%2,%3}, {%4,%5,%6,%7}, {%8,%9}, {%0,%1,%2,%3};"
                : "+f"(acc[nt][0]), "+f"(acc[nt][1]),
                  "+f"(acc[nt][2]), "+f"(acc[nt][3])
                : "r"(a[0]), "r"(a[1]), "r"(a[2]), "r"(a[3]),
                  "r"(b0), "r"(b1v));
        }
    }

    const float* bias = (const float*)(sm + BIAS_OFF);
    const int px_a = px0 + warp*16 + g_;
#pragma unroll
    for (int nt = 0; nt < 8; nt++) {
        int n = nt*8 + tig*2;
        float bx = bias[n], by = bias[n+1];
        float* p0 = g_comp + ((size_t)b*HW_ + px_a) * COMP_ + n;
        *(float2*)p0             = make_float2(acc[nt][0] + bx, acc[nt][1] + by);
        *(float2*)(p0 + 8*COMP_) = make_float2(acc[nt][2] + bx, acc[nt][3] + by);
    }
}

// ================= Kernel B: 3x3 stride-2 conv + fused softmax (f32x2 packed) =================
#define CS_ROW   130
#define CS_CH    (5*CS_ROW)
#define WA_OFF   (COMP_*CS_CH)
#define WB_OFF   (WA_OFF + KK_*COMP_*8)
#define B_SMEM_FLOATS (WB_OFF + KK_*COMP_)
#define B_SMEM_BYTES (B_SMEM_FLOATS*4)

__global__ __launch_bounds__(256) void k_conv2(const float* __restrict__ w2,
                                               const float* __restrict__ b2) {
    extern __shared__ __align__(16) float smemB[];
    float* cs = smemB;
    float* wA = smemB + WA_OFF;
    float* wB = smemB + WB_OFF;
    float* ls = smemB;

    const int b   = blockIdx.y;
    const int hop = blockIdx.x;
    const int tid = threadIdx.x;

    for (int idx = tid; idx < KK_*COMP_*8; idx += 256) {
        int oc = idx >> 3, k = idx & 7;
        wA[idx] = w2[oc*9 + k];
    }
    for (int idx = tid; idx < KK_*COMP_; idx += 256)
        wB[idx] = w2[idx*9 + 8];

    const int r0 = 4*hop - 1;
    for (int idx = tid; idx < COMP_*CS_CH; idx += 256) {
        int c   = idx & 63;
        int pix = idx >> 6;
        int r   = pix / CS_ROW;
        int col = pix - r*CS_ROW;
        int gr = r0 + r, gc = col - 1;
        float v = 0.f;
        if ((unsigned)gr < (unsigned)H_ && (unsigned)gc < (unsigned)W_)
            v = g_comp[((size_t)b*HW_ + gr*W_ + gc) * COMP_ + c];
        cs[c*CS_CH + r*CS_ROW + col] = v;
    }
    __syncthreads();

    const int wo = tid & 63;
    const int og = tid >> 6;
    const int nO = (og == 0) ? 7 : 6;

    unsigned long long accP[7];
#pragma unroll
    for (int t = 0; t < 7; t++) accP[t] = 0ull;

#pragma unroll 1
    for (int c = 0; c < COMP_; c++) {
        const float* csp = cs + c*CS_CH + 2*wo;
        float xv[5][3];
#pragma unroll
        for (int r = 0; r < 5; r++) {
            float2 u = *(const float2*)(csp + r*CS_ROW);
            xv[r][0] = u.x; xv[r][1] = u.y;
            xv[r][2] = csp[r*CS_ROW + 2];
        }
        // xp[k] = (xv[ki][kj], xv[ki+2][kj])  — shared across all 7 outputs
        unsigned long long xp[9];
#pragma unroll
        for (int ki = 0; ki < 3; ki++)
#pragma unroll
            for (int kj = 0; kj < 3; kj++)
                xp[ki*3+kj] = pack2(xv[ki][kj], xv[ki+2][kj]);

#pragma unroll
        for (int t = 0; t < 7; t++) {
            if (t < nO) {
                int o = og + 4*t;
                const float* wa = wA + (o*COMP_ + c)*8;
                float4 v0 = *(const float4*)wa;
                float4 v1 = *(const float4*)(wa + 4);
                float  w8 = wB[o*COMP_ + c];
                fma2(accP[t], dup2(v0.x), xp[0]);
                fma2(accP[t], dup2(v0.y), xp[1]);
                fma2(accP[t], dup2(v0.z), xp[2]);
                fma2(accP[t], dup2(v0.w), xp[3]);
                fma2(accP[t], dup2(v1.x), xp[4]);
                fma2(accP[t], dup2(v1.y), xp[5]);
                fma2(accP[t], dup2(v1.z), xp[6]);
                fma2(accP[t], dup2(v1.w), xp[7]);
                fma2(accP[t], dup2(w8),   xp[8]);
            }
        }
    }

    __syncthreads();
#pragma unroll
    for (int t = 0; t < 7; t++) {
        if (t < nO) {
            int o = og + 4*t;
            float bias = b2[o];
            float2 a = unpack2(accP[t]);
            ls[(     wo)*29 + o] = a.x + bias;
            ls[(64 + wo)*29 + o] = a.y + bias;
        }
    }
    __syncthreads();

    const int ho0 = 2*hop;
    if (tid < 128) {
        const float* lp = ls + tid*29;
        float mx = -1e30f;
#pragma unroll
        for (int o = 0; o < KK_; o++) mx = fmaxf(mx, lp[o]);
        float e[KK_]; float s = 0.f;
#pragma unroll
        for (int o = 0; o < KK_; o++) { e[o] = __expf(lp[o] - mx); s += e[o]; }
        float inv = 1.f / s;
        int ho = ho0 + (tid >> 6);
        int wx = tid & 63;
#pragma unroll
        for (int o = 0; o < KK_; o++)
            g_mask[(((size_t)b*KK_ + o)*HO_ + ho)*WO_ + wx] = e[o] * inv;
    }
}

// ================= Kernel C: CARAFE gather — pipelined, unroll-2 (no rotation) =================
struct RowBuf { float2 a01[5]; float2 a23[5]; float a4[5]; };

__device__ __forceinline__ void load_rows(RowBuf& rb, const float* base0,
                                          const bool* rok, bool okL, bool okR, int r0) {
    const float2 z2 = make_float2(0.f, 0.f);
#pragma unroll
    for (int i = 0; i < 5; i++) {
        const float* base = base0 + (size_t)(r0 + i) * W_;
        rb.a01[i] = (rok[i] && okL) ? __ldg((const float2*)base)       : z2;
        rb.a23[i] =  rok[i]         ? __ldg((const float2*)(base + 2)) : z2;
        rb.a4[i]  = (rok[i] && okR) ? __ldg(base + 4)                  : 0.f;
    }
}
__device__ __forceinline__ float dot_rows(const RowBuf& rb, const float* mw) {
    float a = 0.f;
#pragma unroll
    for (int i = 0; i < 5; i++) {
        a = fmaf(mw[5*i+0], rb.a01[i].x, a);
        a = fmaf(mw[5*i+1], rb.a01[i].y, a);
        a = fmaf(mw[5*i+2], rb.a23[i].x, a);
        a = fmaf(mw[5*i+3], rb.a23[i].y, a);
        a = fmaf(mw[5*i+4], rb.a4[i],    a);
    }
    return a;
}

__global__ __launch_bounds__(256) void k_carafe(const float* __restrict__ x,
                                                float* __restrict__ out) {
    __shared__ float ms[KK_*64];

    const int ho = blockIdx.x;
    const int cq = blockIdx.y;
    const int b  = blockIdx.z;
    const int tid = threadIdx.x;

    for (int idx = tid; idx < KK_*64; idx += 256)
        ms[idx] = g_mask[(((size_t)b*KK_ + (idx >> 6))*HO_ + ho)*WO_ + (idx & 63)];
    __syncthreads();

    const int wo   = tid & 63;
    const int slot = tid >> 6;

    float mw[KK_];
#pragma unroll
    for (int o = 0; o < KK_; o++) mw[o] = ms[o*64 + wo];

    const int r0 = 2*ho - 2;
    const int cL = 2*wo - 2;
    const bool okL = (wo > 0);
    const bool okR = (wo < 63);

    bool rok[5];
#pragma unroll
    for (int i = 0; i < 5; i++) { int r = r0 + i; rok[i] = ((unsigned)r < (unsigned)H_); }

    const float* xc = x + ((size_t)(b*C_ + cq*64 + slot*16)) * HW_ + cL;
    float* ob = out + (((size_t)(b*C_ + cq*64 + slot*16))*HO_ + ho)*WO_ + wo;

    RowBuf A, B;
    load_rows(A, xc, rok, okL, okR, r0);        // channel 0

#pragma unroll 1
    for (int tt = 0; tt < 8; tt++) {
        load_rows(B, xc + HW_, rok, okL, okR, r0);        // channel 2tt+1
        *ob = dot_rows(A, mw);                             // consume channel 2tt
        const float* xn = (tt < 7) ? xc + 2*HW_ : xc;      // channel 2tt+2 (clamped)
        load_rows(A, xn, rok, okL, okR, r0);
        ob[HO_*WO_] = dot_rows(B, mw);                     // consume channel 2tt+1
        xc += 2*HW_;
        ob += 2*HO_*WO_;
    }
}

// ================= launch =================
extern "C" void kernel_launch(void* const* d_in, const int* in_sizes, int n_in,
                              void* d_out, int out_size) {
    const float* x  = (const float*)d_in[0];
    const float* w1 = (const float*)d_in[1];
    const float* b1 = (const float*)d_in[2];
    const float* w2 = (const float*)d_in[3];
    const float* b2 = (const float*)d_in[4];
    float* out = (float*)d_out;

    cudaFuncSetAttribute(k_conv1, cudaFuncAttributeMaxDynamicSharedMemorySize, A_SMEM_BYTES);
    cudaFuncSetAttribute(k_conv2, cudaFuncAttributeMaxDynamicSharedMemorySize, B_SMEM_BYTES);

    k_prep<<<64, 256>>>(w1);
    k_conv1<<<dim3(256, 4), 128, A_SMEM_BYTES>>>(x, b1);
    k_conv2<<<dim3(32, 4), 256, B_SMEM_BYTES>>>(w2, b2);
    k_carafe<<<dim3(64, 4, 4), 256>>>(x, out);
}

// round 12
// speedup vs baseline: 1.1884x; 1.1884x over previous
#include <cuda_runtime.h>
#include <cuda_bf16.h>
#include <cstdint>

#define B_    4
#define C_    256
#define H_    128
#define W_    128
#define HW_   (H_*W_)
#define COMP_ 64
#define KK_   25
#define HO_   64
#define WO_   64

// Scratch (device globals; allocation is forbidden)
__device__ float g_comp[B_*HW_*COMP_];     // [b][px][ch] channel-minor
__device__ float g_mask[B_*KK_*HO_*WO_];   // NORMALIZED softmax weights
__device__ __align__(16) unsigned char g_w1b[COMP_*C_*2];

__device__ __forceinline__ uint32_t smem_u32(const void* p) {
    uint32_t a;
    asm("{ .reg .u64 t; cvta.to.shared.u64 t, %1; cvt.u32.u64 %0, t; }" : "=r"(a) : "l"(p));
    return a;
}
__device__ __forceinline__ unsigned long long dup2(float w) {
    unsigned long long r;
    asm("mov.b64 %0, {%1, %1};" : "=l"(r) : "r"(__float_as_uint(w)));
    return r;
}
__device__ __forceinline__ void fma2(unsigned long long& d,
                                     unsigned long long a, unsigned long long b) {
    asm("fma.rn.f32x2 %0, %1, %2, %0;" : "+l"(d) : "l"(a), "l"(b));
}
__device__ __forceinline__ float2 unpack2(unsigned long long v) {
    unsigned lo, hi;
    asm("mov.b64 {%0, %1}, %2;" : "=r"(lo), "=r"(hi) : "l"(v));
    return make_float2(__uint_as_float(lo), __uint_as_float(hi));
}

// ================= Kernel P: w1 fp32 -> bf16 =================
__global__ void k_prep(const float* __restrict__ w1) {
    int idx = blockIdx.x * 256 + threadIdx.x;
    if (idx < COMP_ * C_)
        ((__nv_bfloat16*)g_w1b)[idx] = __float2bfloat16(w1[idx]);
}

// ================= Kernel A: 1x1 conv via mma.sync bf16 (64-px tiles, R10) =================
#define XS_OFF   0
#define WS_OFF   8192
#define BIAS_OFF (8192 + 32768)
#define A_SMEM_BYTES (BIAS_OFF + 256)

__global__ __launch_bounds__(128) void k_conv1(const float* __restrict__ x,
                                               const float* __restrict__ b1) {
    extern __shared__ __align__(16) char sm[];
    const uint32_t smb = smem_u32(sm);
    const int tid  = threadIdx.x;
    const int warp = tid >> 5;
    const int lane = tid & 31;
    const int b    = blockIdx.y;
    const int px0  = blockIdx.x * 64;

    {
        const uint4* wsrc = (const uint4*)g_w1b;
#pragma unroll
        for (int l = 0; l < 16; l++) {
            int i = l*128 + tid;
            int n = i >> 5, cx = i & 31;
            *(uint4*)(sm + WS_OFF + n*512 + (uint32_t)((cx ^ (n & 7)) << 4)) = wsrc[i];
        }
        if (tid < 64) ((float*)(sm + BIAS_OFF))[tid] = b1[tid];
    }

    float acc[8][4];
#pragma unroll
    for (int nt = 0; nt < 8; nt++)
#pragma unroll
        for (int i = 0; i < 4; i++) acc[nt][i] = 0.f;

    const int lj  = lane & 7;
    const int lg2 = (lane >> 3) & 1;
    const int lg4 = lane >> 4;
    const int g_  = lane >> 2;
    const int tig = lane & 3;

    const float* xbase = x + ((size_t)b * C_) * HW_ + px0;

    for (int chunk = 0; chunk < 4; chunk++) {
        __syncthreads();
        const float4* xsrc = (const float4*)(xbase + (size_t)(chunk * 64) * HW_);
#pragma unroll
        for (int l = 0; l < 8; l++) {
            int id = l*128 + tid;
            int ch = id >> 4, f4 = id & 15;
            float4 v = xsrc[(size_t)ch * (HW_/4) + f4];
            __nv_bfloat162 h0 = __float22bfloat162_rn(make_float2(v.x, v.y));
            __nv_bfloat162 h1 = __float22bfloat162_rn(make_float2(v.z, v.w));
            int cx = f4 >> 1;
            uint32_t off = XS_OFF + ch*128 + (uint32_t)((cx ^ (ch & 7)) << 4) + (f4 & 1) * 8;
            *(uint2*)(sm + off) = make_uint2(*(uint32_t*)&h0, *(uint32_t*)&h1);
        }
        __syncthreads();

#pragma unroll
        for (int s = 0; s < 4; s++) {
            uint32_t a[4];
            const int krow  = s*16 + lj + lg4*8;
            const int pxcol = warp*16 + lg2*8;
            uint32_t addr = smb + XS_OFF + krow*128
                          + (uint32_t)(((pxcol >> 3) ^ (krow & 7)) << 4);
            asm volatile("ldmatrix.sync.aligned.m8n8.x4.trans.shared.b16 "
                         "{%0,%1,%2,%3}, [%4];"
                         : "=r"(a[0]), "=r"(a[1]), "=r"(a[2]), "=r"(a[3])
                         : "r"(addr));
            const int kabs = chunk*64 + s*16;
            const int cx0  = kabs >> 3;
#pragma unroll
            for (int nt = 0; nt < 8; nt++) {
                int n = nt*8 + g_;
                uint32_t ab0 = smb + WS_OFF + n*512
                             + (uint32_t)(((cx0     ) ^ (n & 7)) << 4) + tig*4;
                uint32_t ab1 = smb + WS_OFF + n*512
                             + (uint32_t)(((cx0 + 1) ^ (n & 7)) << 4) + tig*4;
                uint32_t b0, b1v;
                asm volatile("ld.shared.b32 %0, [%1];" : "=r"(b0)  : "r"(ab0));
                asm volatile("ld.shared.b32 %0, [%1];" : "=r"(b1v) : "r"(ab1));
                asm volatile(
                    "mma.sync.aligned.m16n8k16.row.col.f32.bf16.bf16.f32 "
                    "{%0,%1,%2,%3}, {%4,%5,%6,%7}, {%8,%9}, {%0,%1,%2,%3};"
                    : "+f"(acc[nt][0]), "+f"(acc[nt][1]),
                      "+f"(acc[nt][2]), "+f"(acc[nt][3])
                    : "r"(a[0]), "r"(a[1]), "r"(a[2]), "r"(a[3]),
                      "r"(b0), "r"(b1v));
            }
        }
    }

    const float* bias = (const float*)(sm + BIAS_OFF);
    const int px_a = px0 + warp*16 + g_;
#pragma unroll
    for (int nt = 0; nt < 8; nt++) {
        int n = nt*8 + tig*2;
        float bx = bias[n], by = bias[n+1];
        float* p0 = g_comp + ((size_t)b*HW_ + px_a) * COMP_ + n;
        *(float2*)p0             = make_float2(acc[nt][0] + bx, acc[nt][1] + by);
        *(float2*)(p0 + 8*COMP_) = make_float2(acc[nt][2] + bx, acc[nt][3] + by);
    }
}

// ================= Kernel B: 3x3 stride-2 conv + fused softmax =================
// f32x2 packed over OUTPUT PAIRS: weight pairs pre-packed in smem (zero-ALU operand),
// x dup'd once per value. 13 pairs: pair p = outputs (2p, 2p+1); p=12 has dummy hi.
#define CS_ROW   130
#define CS_CH    (5*CS_ROW)
#define NPAIR    13
#define WP_OFF   (COMP_*CS_CH)                        // float index; float2 region after
#define B_SMEM_BYTES (WP_OFF*4 + NPAIR*COMP_*9*8)     // 166400 + 59904 = 226304

__global__ __launch_bounds__(256) void k_conv2(const float* __restrict__ w2,
                                               const float* __restrict__ b2) {
    extern __shared__ __align__(16) float smemB[];
    float*  cs = smemB;
    float2* wP = (float2*)(smemB + WP_OFF);           // [pair][c][k]
    float*  ls = smemB;                               // reused after compute

    const int b   = blockIdx.y;
    const int hop = blockIdx.x;
    const int tid = threadIdx.x;

    // stage packed weight pairs
    for (int idx = tid; idx < NPAIR*COMP_*9; idx += 256) {
        int p   = idx / (COMP_*9);
        int rem = idx - p*(COMP_*9);                  // c*9 + k
        int o0 = 2*p, o1 = 2*p + 1;
        float wlo = w2[o0*(COMP_*9) + rem];
        float whi = (o1 < KK_) ? w2[o1*(COMP_*9) + rem] : 0.f;
        wP[idx] = make_float2(wlo, whi);
    }

    const int r0 = 4*hop - 1;
    for (int idx = tid; idx < COMP_*CS_CH; idx += 256) {
        int c   = idx & 63;
        int pix = idx >> 6;
        int r   = pix / CS_ROW;
        int col = pix - r*CS_ROW;
        int gr = r0 + r, gc = col - 1;
        float v = 0.f;
        if ((unsigned)gr < (unsigned)H_ && (unsigned)gc < (unsigned)W_)
            v = g_comp[((size_t)b*HW_ + gr*W_ + gc) * COMP_ + c];
        cs[c*CS_CH + r*CS_ROW + col] = v;
    }
    __syncthreads();

    const int wo = tid & 63;
    const int og = tid >> 6;                  // pair slots: p = og + 4t
    const int nP = (og == 0) ? 4 : 3;

    unsigned long long accP[4][2];            // [pair slot][row]
#pragma unroll
    for (int t = 0; t < 4; t++) { accP[t][0] = 0ull; accP[t][1] = 0ull; }

#pragma unroll 1
    for (int c = 0; c < COMP_; c++) {
        const float* csp = cs + c*CS_CH + 2*wo;
        float xv[5][3];
#pragma unroll
        for (int r = 0; r < 5; r++) {
            float2 u = *(const float2*)(csp + r*CS_ROW);
            xv[r][0] = u.x; xv[r][1] = u.y;
            xv[r][2] = csp[r*CS_ROW + 2];
        }
        // dup x once per value (CSE'd): xd[r][j] = (xv, xv)
        unsigned long long xd[5][3];
#pragma unroll
        for (int r = 0; r < 5; r++)
#pragma unroll
            for (int j = 0; j < 3; j++) xd[r][j] = dup2(xv[r][j]);

#pragma unroll
        for (int t = 0; t < 4; t++) {
            if (t < nP) {
                int p = og + 4*t;
                const unsigned long long* wpc =
                    (const unsigned long long*)(wP + (p*COMP_ + c)*9);
#pragma unroll
                for (int ki = 0; ki < 3; ki++)
#pragma unroll
                    for (int kj = 0; kj < 3; kj++) {
                        unsigned long long w = wpc[ki*3 + kj];
                        fma2(accP[t][0], w, xd[ki][kj]);       // rows ho0
                        fma2(accP[t][1], w, xd[ki+2][kj]);     // rows ho0+1
                    }
            }
        }
    }

    __syncthreads();          // cs reads done; reuse as ls
#pragma unroll
    for (int t = 0; t < 4; t++) {
        if (t < nP) {
            int p = og + 4*t;
            int o0 = 2*p, o1 = 2*p + 1;
            float2 a0 = unpack2(accP[t][0]);
            float2 a1 = unpack2(accP[t][1]);
            float bz0 = b2[o0];
            ls[(     wo)*29 + o0] = a0.x + bz0;
            ls[(64 + wo)*29 + o0] = a1.x + bz0;
            if (o1 < KK_) {
                float bz1 = b2[o1];
                ls[(     wo)*29 + o1] = a0.y + bz1;
                ls[(64 + wo)*29 + o1] = a1.y + bz1;
            }
        }
    }
    __syncthreads();

    const int ho0 = 2*hop;
    if (tid < 128) {
        const float* lp = ls + tid*29;
        float mx = -1e30f;
#pragma unroll
        for (int o = 0; o < KK_; o++) mx = fmaxf(mx, lp[o]);
        float e[KK_]; float s = 0.f;
#pragma unroll
        for (int o = 0; o < KK_; o++) { e[o] = __expf(lp[o] - mx); s += e[o]; }
        float inv = 1.f / s;
        int ho = ho0 + (tid >> 6);
        int wx = tid & 63;
#pragma unroll
        for (int o = 0; o < KK_; o++)
            g_mask[(((size_t)b*KK_ + o)*HO_ + ho)*WO_ + wx] = e[o] * inv;
    }
}

// ================= Kernel C: CARAFE gather — R9 pipeline (weights via LDS) =================
__global__ __launch_bounds__(256) void k_carafe(const float* __restrict__ x,
                                                float* __restrict__ out) {
    __shared__ float ms[KK_*64];

    const int ho = blockIdx.x;
    const int cq = blockIdx.y;
    const int b  = blockIdx.z;
    const int tid = threadIdx.x;

    for (int idx = tid; idx < KK_*64; idx += 256)
        ms[idx] = g_mask[(((size_t)b*KK_ + (idx >> 6))*HO_ + ho)*WO_ + (idx & 63)];
    __syncthreads();

    const int wo   = tid & 63;
    const int slot = tid >> 6;
    const float* mp = ms + wo;

    const int r0 = 2*ho - 2;
    const int cL = 2*wo - 2;
    const bool okL = (wo > 0);
    const bool okR = (wo < 63);
    const float2 z2 = make_float2(0.f, 0.f);

    bool rok[5];
#pragma unroll
    for (int i = 0; i < 5; i++) { int r = r0 + i; rok[i] = ((unsigned)r < (unsigned)H_); }

    const float* xc = x + ((size_t)(b*C_ + cq*64 + slot*16)) * HW_ + cL;
    float* ob = out + (((size_t)(b*C_ + cq*64 + slot*16))*HO_ + ho)*WO_ + wo;

    float2 a01[5], a23[5]; float a4[5];
#pragma unroll
    for (int i = 0; i < 5; i++) {
        const float* base = xc + (size_t)(r0 + i) * W_;
        a01[i] = (rok[i] && okL) ? __ldg((const float2*)base)       : z2;
        a23[i] =  rok[i]         ? __ldg((const float2*)(base + 2)) : z2;
        a4[i]  = (rok[i] && okR) ? __ldg(base + 4)                  : 0.f;
    }

#pragma unroll 1
    for (int t = 0; t < 16; t++) {
        const float* xn = xc + (t < 15 ? HW_ : 0);
        float2 b01[5], b23[5]; float b4[5];
#pragma unroll
        for (int i = 0; i < 5; i++) {
            const float* base = xn + (size_t)(r0 + i) * W_;
            b01[i] = (rok[i] && okL) ? __ldg((const float2*)base)       : z2;
            b23[i] =  rok[i]         ? __ldg((const float2*)(base + 2)) : z2;
            b4[i]  = (rok[i] && okR) ? __ldg(base + 4)                  : 0.f;
        }

        float a = 0.f;
#pragma unroll
        for (int i = 0; i < 5; i++) {
            a = fmaf(mp[(5*i+0)*64], a01[i].x, a);
            a = fmaf(mp[(5*i+1)*64], a01[i].y, a);
            a = fmaf(mp[(5*i+2)*64], a23[i].x, a);
            a = fmaf(mp[(5*i+3)*64], a23[i].y, a);
            a = fmaf(mp[(5*i+4)*64], a4[i],    a);
        }
        *ob = a;

#pragma unroll
        for (int i = 0; i < 5; i++) { a01[i] = b01[i]; a23[i] = b23[i]; a4[i] = b4[i]; }
        xc += HW_;
        ob += HO_*WO_;
    }
}

// ================= launch =================
extern "C" void kernel_launch(void* const* d_in, const int* in_sizes, int n_in,
                              void* d_out, int out_size) {
    const float* x  = (const float*)d_in[0];
    const float* w1 = (const float*)d_in[1];
    const float* b1 = (const float*)d_in[2];
    const float* w2 = (const float*)d_in[3];
    const float* b2 = (const float*)d_in[4];
    float* out = (float*)d_out;

    cudaFuncSetAttribute(k_conv1, cudaFuncAttributeMaxDynamicSharedMemorySize, A_SMEM_BYTES);
    cudaFuncSetAttribute(k_conv2, cudaFuncAttributeMaxDynamicSharedMemorySize, B_SMEM_BYTES);

    k_prep<<<64, 256>>>(w1);
    k_conv1<<<dim3(256, 4), 128, A_SMEM_BYTES>>>(x, b1);
    k_conv2<<<dim3(32, 4), 256, B_SMEM_BYTES>>>(w2, b2);
    k_carafe<<<dim3(64, 4, 4), 256>>>(x, out);
}

// round 13
// speedup vs baseline: 1.2659x; 1.0652x over previous
#include <cuda_runtime.h>
#include <cuda_bf16.h>
#include <cstdint>

#define B_    4
#define C_    256
#define H_    128
#define W_    128
#define HW_   (H_*W_)
#define COMP_ 64
#define KK_   25
#define HO_   64
#define WO_   64

// Scratch (device globals; allocation is forbidden)
__device__ float g_comp[B_*HW_*COMP_];     // [b][px][ch] channel-minor
__device__ float g_mask[B_*KK_*HO_*WO_];   // NORMALIZED softmax weights
__device__ __align__(16) unsigned char g_w1b[COMP_*C_*2];   // w1 bf16 PRE-SWIZZLED

__device__ __forceinline__ uint32_t smem_u32(const void* p) {
    uint32_t a;
    asm("{ .reg .u64 t; cvta.to.shared.u64 t, %1; cvt.u32.u64 %0, t; }" : "=r"(a) : "l"(p));
    return a;
}
__device__ __forceinline__ unsigned long long dup2(float w) {
    unsigned long long r;
    asm("mov.b64 %0, {%1, %1};" : "=l"(r) : "r"(__float_as_uint(w)));
    return r;
}
__device__ __forceinline__ void fma2(unsigned long long& d,
                                     unsigned long long a, unsigned long long b) {
    asm("fma.rn.f32x2 %0, %1, %2, %0;" : "+l"(d) : "l"(a), "l"(b));
}
__device__ __forceinline__ float2 unpack2(unsigned long long v) {
    unsigned lo, hi;
    asm("mov.b64 {%0, %1}, %2;" : "=r"(lo), "=r"(hi) : "l"(v));
    return make_float2(__uint_as_float(lo), __uint_as_float(hi));
}
__device__ __forceinline__ void cp_async16(uint32_t dst, const void* src) {
    asm volatile("{ .reg .u64 g; cvta.to.global.u64 g, %1; "
                 "cp.async.cg.shared.global [%0], [g], 16; }"
                 :: "r"(dst), "l"(src));
}

// ================= Kernel P: w1 fp32 -> bf16, PRE-SWIZZLED =================
__global__ void k_prep(const float* __restrict__ w1) {
    int idx = blockIdx.x * 256 + threadIdx.x;      // n*256 + k
    if (idx < COMP_ * C_) {
        int n = idx >> 8, k = idx & 255;
        int cx = k >> 3;
        uint32_t off = (uint32_t)(n*512 + ((cx ^ (n & 7)) << 4) + (k & 7)*2);
        *(__nv_bfloat16*)(g_w1b + off) = __float2bfloat16(w1[idx]);
    }
}

// ================= Kernel A: 1x1 conv via mma.sync bf16 (64-px tiles) =================
#define XS_OFF   0
#define WS_OFF   8192
#define BIAS_OFF (8192 + 32768)
#define A_SMEM_BYTES (BIAS_OFF + 256)

__global__ __launch_bounds__(128) void k_conv1(const float* __restrict__ x,
                                               const float* __restrict__ b1) {
    extern __shared__ __align__(16) char sm[];
    const uint32_t smb = smem_u32(sm);
    const int tid  = threadIdx.x;
    const int warp = tid >> 5;
    const int lane = tid & 31;
    const int b    = blockIdx.y;
    const int px0  = blockIdx.x * 64;

    // ws copy: pre-swizzled source -> linear cp.async burst (overlapped)
#pragma unroll
    for (int l = 0; l < 16; l++) {
        int i = l*128 + tid;
        cp_async16(smb + WS_OFF + (uint32_t)i*16, (const char*)g_w1b + (size_t)i*16);
    }
    asm volatile("cp.async.commit_group;" ::: "memory");
    if (tid < 64) ((float*)(sm + BIAS_OFF))[tid] = b1[tid];

    float acc[8][4];
#pragma unroll
    for (int nt = 0; nt < 8; nt++)
#pragma unroll
        for (int i = 0; i < 4; i++) acc[nt][i] = 0.f;

    const int lj  = lane & 7;
    const int lg2 = (lane >> 3) & 1;
    const int lg4 = lane >> 4;
    const int g_  = lane >> 2;
    const int tig = lane & 3;

    const float* xbase = x + ((size_t)b * C_) * HW_ + px0;

    for (int chunk = 0; chunk < 4; chunk++) {
        __syncthreads();
        const float4* xsrc = (const float4*)(xbase + (size_t)(chunk * 64) * HW_);
#pragma unroll
        for (int l = 0; l < 8; l++) {
            int id = l*128 + tid;
            int ch = id >> 4, f4 = id & 15;
            float4 v = xsrc[(size_t)ch * (HW_/4) + f4];
            __nv_bfloat162 h0 = __float22bfloat162_rn(make_float2(v.x, v.y));
            __nv_bfloat162 h1 = __float22bfloat162_rn(make_float2(v.z, v.w));
            int cx = f4 >> 1;
            uint32_t off = XS_OFF + ch*128 + (uint32_t)((cx ^ (ch & 7)) << 4) + (f4 & 1) * 8;
            *(uint2*)(sm + off) = make_uint2(*(uint32_t*)&h0, *(uint32_t*)&h1);
        }
        if (chunk == 0)
            asm volatile("cp.async.wait_group 0;" ::: "memory");
        __syncthreads();

#pragma unroll
        for (int s = 0; s < 4; s++) {
            uint32_t a[4];
            const int krow  = s*16 + lj + lg4*8;
            const int pxcol = warp*16 + lg2*8;
            uint32_t addr = smb + XS_OFF + krow*128
                          + (uint32_t)(((pxcol >> 3) ^ (krow & 7)) << 4);
            asm volatile("ldmatrix.sync.aligned.m8n8.x4.trans.shared.b16 "
                         "{%0,%1,%2,%3}, [%4];"
                         : "=r"(a[0]), "=r"(a[1]), "=r"(a[2]), "=r"(a[3])
                         : "r"(addr));
            const int kabs = chunk*64 + s*16;
            const int cx0  = kabs >> 3;
#pragma unroll
            for (int nt = 0; nt < 8; nt++) {
                int n = nt*8 + g_;
                uint32_t ab0 = smb + WS_OFF + n*512
                             + (uint32_t)(((cx0     ) ^ (n & 7)) << 4) + tig*4;
                uint32_t ab1 = smb + WS_OFF + n*512
                             + (uint32_t)(((cx0 + 1) ^ (n & 7)) << 4) + tig*4;
                uint32_t b0, b1v;
                asm volatile("ld.shared.b32 %0, [%1];" : "=r"(b0)  : "r"(ab0));
                asm volatile("ld.shared.b32 %0, [%1];" : "=r"(b1v) : "r"(ab1));
                asm volatile(
                    "mma.sync.aligned.m16n8k16.row.col.f32.bf16.bf16.f32 "
                    "{%0,%1,%2,%3}, {%4,%5,%6,%7}, {%8,%9}, {%0,%1,%2,%3};"
                    : "+f"(acc[nt][0]), "+f"(acc[nt][1]),
                      "+f"(acc[nt][2]), "+f"(acc[nt][3])
                    : "r"(a[0]), "r"(a[1]), "r"(a[2]), "r"(a[3]),
                      "r"(b0), "r"(b1v));
            }
        }
    }

    const float* bias = (const float*)(sm + BIAS_OFF);
    const int px_a = px0 + warp*16 + g_;
#pragma unroll
    for (int nt = 0; nt < 8; nt++) {
        int n = nt*8 + tig*2;
        float bx = bias[n], by = bias[n+1];
        float* p0 = g_comp + ((size_t)b*HW_ + px_a) * COMP_ + n;
        *(float2*)p0             = make_float2(acc[nt][0] + bx, acc[nt][1] + by);
        *(float2*)(p0 + 8*COMP_) = make_float2(acc[nt][2] + bx, acc[nt][3] + by);
    }
}

// ================= Kernel B: 3x3 stride-2 conv + fused softmax (f32x2 output pairs) =================
#define CS_ROW   130
#define CS_CH    (5*CS_ROW)
#define NPAIR    13
#define WP_OFF   (COMP_*CS_CH)
#define B_SMEM_BYTES (WP_OFF*4 + NPAIR*COMP_*9*8)

__global__ __launch_bounds__(256) void k_conv2(const float* __restrict__ w2,
                                               const float* __restrict__ b2) {
    extern __shared__ __align__(16) float smemB[];
    float*  cs = smemB;
    float2* wP = (float2*)(smemB + WP_OFF);
    float*  ls = smemB;

    const int b   = blockIdx.y;
    const int hop = blockIdx.x;
    const int tid = threadIdx.x;

    for (int idx = tid; idx < NPAIR*COMP_*9; idx += 256) {
        int p   = idx / (COMP_*9);
        int rem = idx - p*(COMP_*9);
        int o0 = 2*p, o1 = 2*p + 1;
        float wlo = w2[o0*(COMP_*9) + rem];
        float whi = (o1 < KK_) ? w2[o1*(COMP_*9) + rem] : 0.f;
        wP[idx] = make_float2(wlo, whi);
    }

    // cs loader: division-free, split interior / border / invalid-row
    const int r0 = 4*hop - 1;
#pragma unroll
    for (int r = 0; r < 5; r++) {
        int gr = r0 + r;
        if ((unsigned)gr < (unsigned)H_) {
            const float* src = g_comp + ((size_t)b*HW_ + (size_t)gr*W_) * COMP_;
#pragma unroll 4
            for (int i = tid; i < 128*64; i += 256) {
                int col = (i >> 6) + 1;          // interior cols 1..128
                int c   = i & 63;
                cs[c*CS_CH + r*CS_ROW + col] = src[(size_t)(col-1)*COMP_ + c];
            }
            if (tid < 128) {
                int c = tid & 63, side = tid >> 6;
                cs[c*CS_CH + r*CS_ROW + side*129] = 0.f;
            }
        } else {
            for (int i = tid; i < 130*64; i += 256) {
                int col = i >> 6, c = i & 63;
                cs[c*CS_CH + r*CS_ROW + col] = 0.f;
            }
        }
    }
    __syncthreads();

    const int wo = tid & 63;
    const int og = tid >> 6;
    const int nP = (og == 0) ? 4 : 3;

    unsigned long long accP[4][2];
#pragma unroll
    for (int t = 0; t < 4; t++) { accP[t][0] = 0ull; accP[t][1] = 0ull; }

#pragma unroll 1
    for (int c = 0; c < COMP_; c++) {
        const float* csp = cs + c*CS_CH + 2*wo;
        float xv[5][3];
#pragma unroll
        for (int r = 0; r < 5; r++) {
            float2 u = *(const float2*)(csp + r*CS_ROW);
            xv[r][0] = u.x; xv[r][1] = u.y;
            xv[r][2] = csp[r*CS_ROW + 2];
        }
        unsigned long long xd[5][3];
#pragma unroll
        for (int r = 0; r < 5; r++)
#pragma unroll
            for (int j = 0; j < 3; j++) xd[r][j] = dup2(xv[r][j]);

#pragma unroll
        for (int t = 0; t < 4; t++) {
            if (t < nP) {
                int p = og + 4*t;
                const unsigned long long* wpc =
                    (const unsigned long long*)(wP + (p*COMP_ + c)*9);
#pragma unroll
                for (int ki = 0; ki < 3; ki++)
#pragma unroll
                    for (int kj = 0; kj < 3; kj++) {
                        unsigned long long w = wpc[ki*3 + kj];
                        fma2(accP[t][0], w, xd[ki][kj]);
                        fma2(accP[t][1], w, xd[ki+2][kj]);
                    }
            }
        }
    }

    __syncthreads();
#pragma unroll
    for (int t = 0; t < 4; t++) {
        if (t < nP) {
            int p = og + 4*t;
            int o0 = 2*p, o1 = 2*p + 1;
            float2 a0 = unpack2(accP[t][0]);
            float2 a1 = unpack2(accP[t][1]);
            float bz0 = b2[o0];
            ls[(     wo)*29 + o0] = a0.x + bz0;
            ls[(64 + wo)*29 + o0] = a1.x + bz0;
            if (o1 < KK_) {
                float bz1 = b2[o1];
                ls[(     wo)*29 + o1] = a0.y + bz1;
                ls[(64 + wo)*29 + o1] = a1.y + bz1;
            }
        }
    }
    __syncthreads();

    const int ho0 = 2*hop;
    if (tid < 128) {
        const float* lp = ls + tid*29;
        float mx = -1e30f;
#pragma unroll
        for (int o = 0; o < KK_; o++) mx = fmaxf(mx, lp[o]);
        float e[KK_]; float s = 0.f;
#pragma unroll
        for (int o = 0; o < KK_; o++) { e[o] = __expf(lp[o] - mx); s += e[o]; }
        float inv = 1.f / s;
        int ho = ho0 + (tid >> 6);
        int wx = tid & 63;
#pragma unroll
        for (int o = 0; o < KK_; o++)
            g_mask[(((size_t)b*KK_ + o)*HO_ + ho)*WO_ + wx] = e[o] * inv;
    }
}

// ================= Kernel C: CARAFE gather — pipelined, HYBRID weights =================
// 12 weights in registers + 13 via conflict-free LDS: interior point of the
// L1-wavefront vs occupancy iso-curve (R9 all-LDS == R10 all-reg == 41us).
#define NREG 12
#define MW(t) ((t) < NREG ? mwr[(t) < NREG ? (t) : 0] : mp[(t)*64])

__global__ __launch_bounds__(256) void k_carafe(const float* __restrict__ x,
                                                float* __restrict__ out) {
    __shared__ float ms[KK_*64];

    const int ho = blockIdx.x;
    const int cq = blockIdx.y;
    const int b  = blockIdx.z;
    const int tid = threadIdx.x;

    for (int idx = tid; idx < KK_*64; idx += 256)
        ms[idx] = g_mask[(((size_t)b*KK_ + (idx >> 6))*HO_ + ho)*WO_ + (idx & 63)];
    __syncthreads();

    const int wo   = tid & 63;
    const int slot = tid >> 6;
    const float* mp = ms + wo;

    float mwr[NREG];
#pragma unroll
    for (int o = 0; o < NREG; o++) mwr[o] = ms[o*64 + wo];

    const int r0 = 2*ho - 2;
    const int cL = 2*wo - 2;
    const bool okL = (wo > 0);
    const bool okR = (wo < 63);
    const float2 z2 = make_float2(0.f, 0.f);

    bool rok[5];
#pragma unroll
    for (int i = 0; i < 5; i++) { int r = r0 + i; rok[i] = ((unsigned)r < (unsigned)H_); }

    const float* xc = x + ((size_t)(b*C_ + cq*64 + slot*16)) * HW_ + cL;
    float* ob = out + (((size_t)(b*C_ + cq*64 + slot*16))*HO_ + ho)*WO_ + wo;

    float2 a01[5], a23[5]; float a4[5];
#pragma unroll
    for (int i = 0; i < 5; i++) {
        const float* base = xc + (size_t)(r0 + i) * W_;
        a01[i] = (rok[i] && okL) ? __ldg((const float2*)base)       : z2;
        a23[i] =  rok[i]         ? __ldg((const float2*)(base + 2)) : z2;
        a4[i]  = (rok[i] && okR) ? __ldg(base + 4)                  : 0.f;
    }

#pragma unroll 1
    for (int t = 0; t < 16; t++) {
        const float* xn = xc + (t < 15 ? HW_ : 0);
        float2 b01[5], b23[5]; float b4[5];
#pragma unroll
        for (int i = 0; i < 5; i++) {
            const float* base = xn + (size_t)(r0 + i) * W_;
            b01[i] = (rok[i] && okL) ? __ldg((const float2*)base)       : z2;
            b23[i] =  rok[i]         ? __ldg((const float2*)(base + 2)) : z2;
            b4[i]  = (rok[i] && okR) ? __ldg(base + 4)                  : 0.f;
        }

        float a = 0.f;
#pragma unroll
        for (int i = 0; i < 5; i++) {
            a = fmaf(MW(5*i+0), a01[i].x, a);
            a = fmaf(MW(5*i+1), a01[i].y, a);
            a = fmaf(MW(5*i+2), a23[i].x, a);
            a = fmaf(MW(5*i+3), a23[i].y, a);
            a = fmaf(MW(5*i+4), a4[i],    a);
        }
        *ob = a;

#pragma unroll
        for (int i = 0; i < 5; i++) { a01[i] = b01[i]; a23[i] = b23[i]; a4[i] = b4[i]; }
        xc += HW_;
        ob += HO_*WO_;
    }
}

// ================= launch =================
extern "C" void kernel_launch(void* const* d_in, const int* in_sizes, int n_in,
                              void* d_out, int out_size) {
    const float* x  = (const float*)d_in[0];
    const float* w1 = (const float*)d_in[1];
    const float* b1 = (const float*)d_in[2];
    const float* w2 = (const float*)d_in[3];
    const float* b2 = (const float*)d_in[4];
    float* out = (float*)d_out;

    cudaFuncSetAttribute(k_conv1, cudaFuncAttributeMaxDynamicSharedMemorySize, A_SMEM_BYTES);
    cudaFuncSetAttribute(k_conv2, cudaFuncAttributeMaxDynamicSharedMemorySize, B_SMEM_BYTES);

    k_prep<<<64, 256>>>(w1);
    k_conv1<<<dim3(256, 4), 128, A_SMEM_BYTES>>>(x, b1);
    k_conv2<<<dim3(32, 4), 256, B_SMEM_BYTES>>>(w2, b2);
    k_carafe<<<dim3(64, 4, 4), 256>>>(x, out);
}

// round 14
// speedup vs baseline: 1.2837x; 1.0141x over previous
#include <cuda_runtime.h>
#include <cuda_bf16.h>
#include <cstdint>

#define B_    4
#define C_    256
#define H_    128
#define W_    128
#define HW_   (H_*W_)
#define COMP_ 64
#define KK_   25
#define HO_   64
#define WO_   64

// Scratch (device globals; allocation is forbidden)
__device__ float g_comp[B_*HW_*COMP_];     // [b][px][ch] channel-minor
__device__ float g_mask[B_*KK_*HO_*WO_];   // NORMALIZED softmax weights
__device__ __align__(16) unsigned char g_w1b[COMP_*C_*2];   // w1 bf16 PRE-SWIZZLED

__device__ __forceinline__ uint32_t smem_u32(const void* p) {
    uint32_t a;
    asm("{ .reg .u64 t; cvta.to.shared.u64 t, %1; cvt.u32.u64 %0, t; }" : "=r"(a) : "l"(p));
    return a;
}
__device__ __forceinline__ unsigned long long pack2(float lo, float hi) {
    unsigned long long r;
    asm("mov.b64 %0, {%1, %2};" : "=l"(r)
        : "r"(__float_as_uint(lo)), "r"(__float_as_uint(hi)));
    return r;
}
__device__ __forceinline__ unsigned long long dup2(float w) {
    unsigned long long r;
    asm("mov.b64 %0, {%1, %1};" : "=l"(r) : "r"(__float_as_uint(w)));
    return r;
}
__device__ __forceinline__ void fma2(unsigned long long& d,
                                     unsigned long long a, unsigned long long b) {
    asm("fma.rn.f32x2 %0, %1, %2, %0;" : "+l"(d) : "l"(a), "l"(b));
}
__device__ __forceinline__ float2 unpack2(unsigned long long v) {
    unsigned lo, hi;
    asm("mov.b64 {%0, %1}, %2;" : "=r"(lo), "=r"(hi) : "l"(v));
    return make_float2(__uint_as_float(lo), __uint_as_float(hi));
}
__device__ __forceinline__ void cp_async16(uint32_t dst, const void* src) {
    asm volatile("{ .reg .u64 g; cvta.to.global.u64 g, %1; "
                 "cp.async.cg.shared.global [%0], [g], 16; }"
                 :: "r"(dst), "l"(src));
}

// ================= Kernel P: w1 fp32 -> bf16, PRE-SWIZZLED =================
__global__ void k_prep(const float* __restrict__ w1) {
    int idx = blockIdx.x * 256 + threadIdx.x;      // n*256 + k
    if (idx < COMP_ * C_) {
        int n = idx >> 8, k = idx & 255;
        int cx = k >> 3;
        uint32_t off = (uint32_t)(n*512 + ((cx ^ (n & 7)) << 4) + (k & 7)*2);
        *(__nv_bfloat16*)(g_w1b + off) = __float2bfloat16(w1[idx]);
    }
}

// ================= Kernel A: 1x1 conv via mma.sync bf16 (64-px tiles) =================
#define XS_OFF   0
#define WS_OFF   8192
#define BIAS_OFF (8192 + 32768)
#define A_SMEM_BYTES (BIAS_OFF + 256)

__global__ __launch_bounds__(128) void k_conv1(const float* __restrict__ x,
                                               const float* __restrict__ b1) {
    extern __shared__ __align__(16) char sm[];
    const uint32_t smb = smem_u32(sm);
    const int tid  = threadIdx.x;
    const int warp = tid >> 5;
    const int lane = tid & 31;
    const int b    = blockIdx.y;
    const int px0  = blockIdx.x * 64;

#pragma unroll
    for (int l = 0; l < 16; l++) {
        int i = l*128 + tid;
        cp_async16(smb + WS_OFF + (uint32_t)i*16, (const char*)g_w1b + (size_t)i*16);
    }
    asm volatile("cp.async.commit_group;" ::: "memory");
    if (tid < 64) ((float*)(sm + BIAS_OFF))[tid] = b1[tid];

    float acc[8][4];
#pragma unroll
    for (int nt = 0; nt < 8; nt++)
#pragma unroll
        for (int i = 0; i < 4; i++) acc[nt][i] = 0.f;

    const int lj  = lane & 7;
    const int lg2 = (lane >> 3) & 1;
    const int lg4 = lane >> 4;
    const int g_  = lane >> 2;
    const int tig = lane & 3;

    const float* xbase = x + ((size_t)b * C_) * HW_ + px0;

    for (int chunk = 0; chunk < 4; chunk++) {
        __syncthreads();
        const float4* xsrc = (const float4*)(xbase + (size_t)(chunk * 64) * HW_);
#pragma unroll
        for (int l = 0; l < 8; l++) {
            int id = l*128 + tid;
            int ch = id >> 4, f4 = id & 15;
            float4 v = xsrc[(size_t)ch * (HW_/4) + f4];
            __nv_bfloat162 h0 = __float22bfloat162_rn(make_float2(v.x, v.y));
            __nv_bfloat162 h1 = __float22bfloat162_rn(make_float2(v.z, v.w));
            int cx = f4 >> 1;
            uint32_t off = XS_OFF + ch*128 + (uint32_t)((cx ^ (ch & 7)) << 4) + (f4 & 1) * 8;
            *(uint2*)(sm + off) = make_uint2(*(uint32_t*)&h0, *(uint32_t*)&h1);
        }
        if (chunk == 0)
            asm volatile("cp.async.wait_group 0;" ::: "memory");
        __syncthreads();

#pragma unroll
        for (int s = 0; s < 4; s++) {
            uint32_t a[4];
            const int krow  = s*16 + lj + lg4*8;
            const int pxcol = warp*16 + lg2*8;
            uint32_t addr = smb + XS_OFF + krow*128
                          + (uint32_t)(((pxcol >> 3) ^ (krow & 7)) << 4);
            asm volatile("ldmatrix.sync.aligned.m8n8.x4.trans.shared.b16 "
                         "{%0,%1,%2,%3}, [%4];"
                         : "=r"(a[0]), "=r"(a[1]), "=r"(a[2]), "=r"(a[3])
                         : "r"(addr));
            const int kabs = chunk*64 + s*16;
            const int cx0  = kabs >> 3;
#pragma unroll
            for (int nt = 0; nt < 8; nt++) {
                int n = nt*8 + g_;
                uint32_t ab0 = smb + WS_OFF + n*512
                             + (uint32_t)(((cx0     ) ^ (n & 7)) << 4) + tig*4;
                uint32_t ab1 = smb + WS_OFF + n*512
                             + (uint32_t)(((cx0 + 1) ^ (n & 7)) << 4) + tig*4;
                uint32_t b0, b1v;
                asm volatile("ld.shared.b32 %0, [%1];" : "=r"(b0)  : "r"(ab0));
                asm volatile("ld.shared.b32 %0, [%1];" : "=r"(b1v) : "r"(ab1));
                asm volatile(
                    "mma.sync.aligned.m16n8k16.row.col.f32.bf16.bf16.f32 "
                    "{%0,%1,%2,%3}, {%4,%5,%6,%7}, {%8,%9}, {%0,%1,%2,%3};"
                    : "+f"(acc[nt][0]), "+f"(acc[nt][1]),
                      "+f"(acc[nt][2]), "+f"(acc[nt][3])
                    : "r"(a[0]), "r"(a[1]), "r"(a[2]), "r"(a[3]),
                      "r"(b0), "r"(b1v));
            }
        }
    }

    const float* bias = (const float*)(sm + BIAS_OFF);
    const int px_a = px0 + warp*16 + g_;
#pragma unroll
    for (int nt = 0; nt < 8; nt++) {
        int n = nt*8 + tig*2;
        float bx = bias[n], by = bias[n+1];
        float* p0 = g_comp + ((size_t)b*HW_ + px_a) * COMP_ + n;
        *(float2*)p0             = make_float2(acc[nt][0] + bx, acc[nt][1] + by);
        *(float2*)(p0 + 8*COMP_) = make_float2(acc[nt][2] + bx, acc[nt][3] + by);
    }
}

// ================= Kernel B: 3x3 stride-2 conv + fused softmax (f32x2 output pairs) =================
#define CS_ROW   130
#define CS_CH    (5*CS_ROW)
#define NPAIR    13
#define WP_OFF   (COMP_*CS_CH)
#define B_SMEM_BYTES (WP_OFF*4 + NPAIR*COMP_*9*8)

__global__ __launch_bounds__(256) void k_conv2(const float* __restrict__ w2,
                                               const float* __restrict__ b2) {
    extern __shared__ __align__(16) float smemB[];
    float*  cs = smemB;
    float2* wP = (float2*)(smemB + WP_OFF);
    float*  ls = smemB;

    const int b   = blockIdx.y;
    const int hop = blockIdx.x;
    const int tid = threadIdx.x;

    for (int idx = tid; idx < NPAIR*COMP_*9; idx += 256) {
        int p   = idx / (COMP_*9);
        int rem = idx - p*(COMP_*9);
        int o0 = 2*p, o1 = 2*p + 1;
        float wlo = w2[o0*(COMP_*9) + rem];
        float whi = (o1 < KK_) ? w2[o1*(COMP_*9) + rem] : 0.f;
        wP[idx] = make_float2(wlo, whi);
    }

    const int r0 = 4*hop - 1;
#pragma unroll
    for (int r = 0; r < 5; r++) {
        int gr = r0 + r;
        if ((unsigned)gr < (unsigned)H_) {
            const float* src = g_comp + ((size_t)b*HW_ + (size_t)gr*W_) * COMP_;
#pragma unroll 4
            for (int i = tid; i < 128*64; i += 256) {
                int col = (i >> 6) + 1;
                int c   = i & 63;
                cs[c*CS_CH + r*CS_ROW + col] = src[(size_t)(col-1)*COMP_ + c];
            }
            if (tid < 128) {
                int c = tid & 63, side = tid >> 6;
                cs[c*CS_CH + r*CS_ROW + side*129] = 0.f;
            }
        } else {
            for (int i = tid; i < 130*64; i += 256) {
                int col = i >> 6, c = i & 63;
                cs[c*CS_CH + r*CS_ROW + col] = 0.f;
            }
        }
    }
    __syncthreads();

    const int wo = tid & 63;
    const int og = tid >> 6;
    const int nP = (og == 0) ? 4 : 3;

    unsigned long long accP[4][2];
#pragma unroll
    for (int t = 0; t < 4; t++) { accP[t][0] = 0ull; accP[t][1] = 0ull; }

#pragma unroll 1
    for (int c = 0; c < COMP_; c++) {
        const float* csp = cs + c*CS_CH + 2*wo;
        float xv[5][3];
#pragma unroll
        for (int r = 0; r < 5; r++) {
            float2 u = *(const float2*)(csp + r*CS_ROW);
            xv[r][0] = u.x; xv[r][1] = u.y;
            xv[r][2] = csp[r*CS_ROW + 2];
        }
        unsigned long long xd[5][3];
#pragma unroll
        for (int r = 0; r < 5; r++)
#pragma unroll
            for (int j = 0; j < 3; j++) xd[r][j] = dup2(xv[r][j]);

#pragma unroll
        for (int t = 0; t < 4; t++) {
            if (t < nP) {
                int p = og + 4*t;
                const unsigned long long* wpc =
                    (const unsigned long long*)(wP + (p*COMP_ + c)*9);
#pragma unroll
                for (int ki = 0; ki < 3; ki++)
#pragma unroll
                    for (int kj = 0; kj < 3; kj++) {
                        unsigned long long w = wpc[ki*3 + kj];
                        fma2(accP[t][0], w, xd[ki][kj]);
                        fma2(accP[t][1], w, xd[ki+2][kj]);
                    }
            }
        }
    }

    __syncthreads();
#pragma unroll
    for (int t = 0; t < 4; t++) {
        if (t < nP) {
            int p = og + 4*t;
            int o0 = 2*p, o1 = 2*p + 1;
            float2 a0 = unpack2(accP[t][0]);
            float2 a1 = unpack2(accP[t][1]);
            float bz0 = b2[o0];
            ls[(     wo)*29 + o0] = a0.x + bz0;
            ls[(64 + wo)*29 + o0] = a1.x + bz0;
            if (o1 < KK_) {
                float bz1 = b2[o1];
                ls[(     wo)*29 + o1] = a0.y + bz1;
                ls[(64 + wo)*29 + o1] = a1.y + bz1;
            }
        }
    }
    __syncthreads();

    const int ho0 = 2*hop;
    if (tid < 128) {
        const float* lp = ls + tid*29;
        float mx = -1e30f;
#pragma unroll
        for (int o = 0; o < KK_; o++) mx = fmaxf(mx, lp[o]);
        float e[KK_]; float s = 0.f;
#pragma unroll
        for (int o = 0; o < KK_; o++) { e[o] = __expf(lp[o] - mx); s += e[o]; }
        float inv = 1.f / s;
        int ho = ho0 + (tid >> 6);
        int wx = tid & 63;
#pragma unroll
        for (int o = 0; o < KK_; o++)
            g_mask[(((size_t)b*KK_ + o)*HO_ + ho)*WO_ + wx] = e[o] * inv;
    }
}

// ================= Kernel C: CARAFE gather — output-pair f32x2, pipelined =================
// Thread = (pair p: outputs 2p,2p+1 ; slot: 8 channels). Weight pairs are adjacent
// in smem -> free 64-bit LDS operands (12 cached in regs). Per row load
// v[0..6] = cols 4p-2..4p+4 (float2 + float4 + float). 25 FMA2 per 2 outputs.
#define NREGW 12

__global__ __launch_bounds__(256) void k_carafe(const float* __restrict__ x,
                                                float* __restrict__ out) {
    __shared__ __align__(16) float ms[KK_*64];

    const int ho = blockIdx.x;
    const int cq = blockIdx.y;
    const int b  = blockIdx.z;
    const int tid = threadIdx.x;

    for (int idx = tid; idx < KK_*64; idx += 256)
        ms[idx] = g_mask[(((size_t)b*KK_ + (idx >> 6))*HO_ + ho)*WO_ + (idx & 63)];
    __syncthreads();

    const int p    = tid & 31;    // output pair: wo = 2p, 2p+1
    const int slot = tid >> 5;    // 8 slots x 8 channels

    const unsigned long long* wp = (const unsigned long long*)(ms + 2*p);
    unsigned long long wreg[NREGW];
#pragma unroll
    for (int o = 0; o < NREGW; o++) wreg[o] = wp[o*32];   // 8B-aligned LDS64

    const int r0 = 2*ho - 2;
    const int cb = 4*p - 2;                // col of v[0]
    const bool okL = (p > 0);
    const bool okR = (p < 31);
    const float2 z2 = make_float2(0.f, 0.f);
    const float4 z4 = make_float4(0.f, 0.f, 0.f, 0.f);

    bool rok[5];
#pragma unroll
    for (int i = 0; i < 5; i++) { int r = r0 + i; rok[i] = ((unsigned)r < (unsigned)H_); }

    const int c0 = cq*64 + slot*8;
    const float* xc = x + ((size_t)(b*C_ + c0)) * HW_ + cb;
    float* ob = out + (((size_t)(b*C_ + c0))*HO_ + ho)*WO_ + 2*p;

    float2 L0[2][5]; float4 L1[2][5]; float L2[2][5];

    // prefetch channel 0
#pragma unroll
    for (int i = 0; i < 5; i++) {
        const float* base = xc + (size_t)(r0 + i) * W_;
        L0[0][i] = (rok[i] && okL) ? __ldg((const float2*)base)       : z2;   // 4p-2,4p-1 (8B aligned)
        L1[0][i] =  rok[i]         ? __ldg((const float4*)(base + 2)) : z4;   // 4p..4p+3 (16B aligned)
        L2[0][i] = (rok[i] && okR) ? __ldg(base + 6)                  : 0.f;  // 4p+4
    }

#pragma unroll
    for (int t = 0; t < 8; t++) {
        const int cur = t & 1, nxt = cur ^ 1;
        if (t < 7) {
            const float* xn = xc + (size_t)(t + 1) * HW_;
#pragma unroll
            for (int i = 0; i < 5; i++) {
                const float* base = xn + (size_t)(r0 + i) * W_;
                L0[nxt][i] = (rok[i] && okL) ? __ldg((const float2*)base)       : z2;
                L1[nxt][i] =  rok[i]         ? __ldg((const float4*)(base + 2)) : z4;
                L2[nxt][i] = (rok[i] && okR) ? __ldg(base + 6)                  : 0.f;
            }
        }

        unsigned long long acc = 0ull;
#pragma unroll
        for (int i = 0; i < 5; i++) {
            const float v0 = L0[cur][i].x, v1 = L0[cur][i].y;
            const float v2 = L1[cur][i].x, v3 = L1[cur][i].y;
            const float v4 = L1[cur][i].z, v5 = L1[cur][i].w;
            const float v6 = L2[cur][i];
            // tap o = 5i+j : acc += (w[o][2p], w[o][2p+1]) * (v[j], v[j+2])
            {
                unsigned long long w;
                w = (5*i+0 < NREGW) ? wreg[(5*i+0) < NREGW ? (5*i+0) : 0] : wp[(5*i+0)*32];
                fma2(acc, w, pack2(v0, v2));
                w = (5*i+1 < NREGW) ? wreg[(5*i+1) < NREGW ? (5*i+1) : 0] : wp[(5*i+1)*32];
                fma2(acc, w, pack2(v1, v3));
                w = (5*i+2 < NREGW) ? wreg[(5*i+2) < NREGW ? (5*i+2) : 0] : wp[(5*i+2)*32];
                fma2(acc, w, pack2(v2, v4));
                w = (5*i+3 < NREGW) ? wreg[(5*i+3) < NREGW ? (5*i+3) : 0] : wp[(5*i+3)*32];
                fma2(acc, w, pack2(v3, v5));
                w = (5*i+4 < NREGW) ? wreg[(5*i+4) < NREGW ? (5*i+4) : 0] : wp[(5*i+4)*32];
                fma2(acc, w, pack2(v4, v6));
            }
        }
        float2 o2 = unpack2(acc);
        *(float2*)(ob + (size_t)t * HO_*WO_) = o2;       // coalesced (lanes stride 8B)
    }
}

// ================= launch =================
extern "C" void kernel_launch(void* const* d_in, const int* in_sizes, int n_in,
                              void* d_out, int out_size) {
    const float* x  = (const float*)d_in[0];
    const float* w1 = (const float*)d_in[1];
    const float* b1 = (const float*)d_in[2];
    const float* w2 = (const float*)d_in[3];
    const float* b2 = (const float*)d_in[4];
    float* out = (float*)d_out;

    cudaFuncSetAttribute(k_conv1, cudaFuncAttributeMaxDynamicSharedMemorySize, A_SMEM_BYTES);
    cudaFuncSetAttribute(k_conv2, cudaFuncAttributeMaxDynamicSharedMemorySize, B_SMEM_BYTES);

    k_prep<<<64, 256>>>(w1);
    k_conv1<<<dim3(256, 4), 128, A_SMEM_BYTES>>>(x, b1);
    k_conv2<<<dim3(32, 4), 256, B_SMEM_BYTES>>>(w2, b2);
    k_carafe<<<dim3(64, 4, 4), 256>>>(x, out);
}

// round 15
// speedup vs baseline: 1.3234x; 1.0309x over previous
#include <cuda_runtime.h>
#include <cuda_bf16.h>
#include <cstdint>

#define B_    4
#define C_    256
#define H_    128
#define W_    128
#define HW_   (H_*W_)
#define COMP_ 64
#define KK_   25
#define HO_   64
#define WO_   64

// Scratch (device globals; allocation is forbidden)
__device__ float g_comp[B_*HW_*COMP_];     // [b][px][ch] channel-minor
__device__ float g_mask[B_*KK_*HO_*WO_];   // NORMALIZED softmax weights
__device__ __align__(16) unsigned char g_w1b[COMP_*C_*2];   // w1 bf16 PRE-SWIZZLED

__device__ __forceinline__ uint32_t smem_u32(const void* p) {
    uint32_t a;
    asm("{ .reg .u64 t; cvta.to.shared.u64 t, %1; cvt.u32.u64 %0, t; }" : "=r"(a) : "l"(p));
    return a;
}
__device__ __forceinline__ unsigned long long pack2(float lo, float hi) {
    unsigned long long r;
    asm("mov.b64 %0, {%1, %2};" : "=l"(r)
        : "r"(__float_as_uint(lo)), "r"(__float_as_uint(hi)));
    return r;
}
__device__ __forceinline__ unsigned long long dup2(float w) {
    unsigned long long r;
    asm("mov.b64 %0, {%1, %1};" : "=l"(r) : "r"(__float_as_uint(w)));
    return r;
}
__device__ __forceinline__ void fma2(unsigned long long& d,
                                     unsigned long long a, unsigned long long b) {
    asm("fma.rn.f32x2 %0, %1, %2, %0;" : "+l"(d) : "l"(a), "l"(b));
}
__device__ __forceinline__ float2 unpack2(unsigned long long v) {
    unsigned lo, hi;
    asm("mov.b64 {%0, %1}, %2;" : "=r"(lo), "=r"(hi) : "l"(v));
    return make_float2(__uint_as_float(lo), __uint_as_float(hi));
}
__device__ __forceinline__ void cp_async16(uint32_t dst, const void* src) {
    asm volatile("{ .reg .u64 g; cvta.to.global.u64 g, %1; "
                 "cp.async.cg.shared.global [%0], [g], 16; }"
                 :: "r"(dst), "l"(src));
}

// ================= Kernel P: w1 fp32 -> bf16, PRE-SWIZZLED =================
__global__ void k_prep(const float* __restrict__ w1) {
    int idx = blockIdx.x * 256 + threadIdx.x;      // n*256 + k
    if (idx < COMP_ * C_) {
        int n = idx >> 8, k = idx & 255;
        int cx = k >> 3;
        uint32_t off = (uint32_t)(n*512 + ((cx ^ (n & 7)) << 4) + (k & 7)*2);
        *(__nv_bfloat16*)(g_w1b + off) = __float2bfloat16(w1[idx]);
    }
}

// ================= Kernel A: 1x1 conv via mma.sync bf16 (64-px tiles) =================
#define XS_OFF   0
#define WS_OFF   8192
#define BIAS_OFF (8192 + 32768)
#define A_SMEM_BYTES (BIAS_OFF + 256)

__global__ __launch_bounds__(128) void k_conv1(const float* __restrict__ x,
                                               const float* __restrict__ b1) {
    extern __shared__ __align__(16) char sm[];
    const uint32_t smb = smem_u32(sm);
    const int tid  = threadIdx.x;
    const int warp = tid >> 5;
    const int lane = tid & 31;
    const int b    = blockIdx.y;
    const int px0  = blockIdx.x * 64;

#pragma unroll
    for (int l = 0; l < 16; l++) {
        int i = l*128 + tid;
        cp_async16(smb + WS_OFF + (uint32_t)i*16, (const char*)g_w1b + (size_t)i*16);
    }
    asm volatile("cp.async.commit_group;" ::: "memory");
    if (tid < 64) ((float*)(sm + BIAS_OFF))[tid] = b1[tid];

    float acc[8][4];
#pragma unroll
    for (int nt = 0; nt < 8; nt++)
#pragma unroll
        for (int i = 0; i < 4; i++) acc[nt][i] = 0.f;

    const int lj  = lane & 7;
    const int lg2 = (lane >> 3) & 1;
    const int lg4 = lane >> 4;
    const int g_  = lane >> 2;
    const int tig = lane & 3;

    const float* xbase = x + ((size_t)b * C_) * HW_ + px0;

    for (int chunk = 0; chunk < 4; chunk++) {
        __syncthreads();
        const float4* xsrc = (const float4*)(xbase + (size_t)(chunk * 64) * HW_);
#pragma unroll
        for (int l = 0; l < 8; l++) {
            int id = l*128 + tid;
            int ch = id >> 4, f4 = id & 15;
            float4 v = xsrc[(size_t)ch * (HW_/4) + f4];
            __nv_bfloat162 h0 = __float22bfloat162_rn(make_float2(v.x, v.y));
            __nv_bfloat162 h1 = __float22bfloat162_rn(make_float2(v.z, v.w));
            int cx = f4 >> 1;
            uint32_t off = XS_OFF + ch*128 + (uint32_t)((cx ^ (ch & 7)) << 4) + (f4 & 1) * 8;
            *(uint2*)(sm + off) = make_uint2(*(uint32_t*)&h0, *(uint32_t*)&h1);
        }
        if (chunk == 0)
            asm volatile("cp.async.wait_group 0;" ::: "memory");
        __syncthreads();

#pragma unroll
        for (int s = 0; s < 4; s++) {
            uint32_t a[4];
            const int krow  = s*16 + lj + lg4*8;
            const int pxcol = warp*16 + lg2*8;
            uint32_t addr = smb + XS_OFF + krow*128
                          + (uint32_t)(((pxcol >> 3) ^ (krow & 7)) << 4);
            asm volatile("ldmatrix.sync.aligned.m8n8.x4.trans.shared.b16 "
                         "{%0,%1,%2,%3}, [%4];"
                         : "=r"(a[0]), "=r"(a[1]), "=r"(a[2]), "=r"(a[3])
                         : "r"(addr));
            const int kabs = chunk*64 + s*16;
            const int cx0  = kabs >> 3;
#pragma unroll
            for (int nt = 0; nt < 8; nt++) {
                int n = nt*8 + g_;
                uint32_t ab0 = smb + WS_OFF + n*512
                             + (uint32_t)(((cx0     ) ^ (n & 7)) << 4) + tig*4;
                uint32_t ab1 = smb + WS_OFF + n*512
                             + (uint32_t)(((cx0 + 1) ^ (n & 7)) << 4) + tig*4;
                uint32_t b0, b1v;
                asm volatile("ld.shared.b32 %0, [%1];" : "=r"(b0)  : "r"(ab0));
                asm volatile("ld.shared.b32 %0, [%1];" : "=r"(b1v) : "r"(ab1));
                asm volatile(
                    "mma.sync.aligned.m16n8k16.row.col.f32.bf16.bf16.f32 "
                    "{%0,%1,%2,%3}, {%4,%5,%6,%7}, {%8,%9}, {%0,%1,%2,%3};"
                    : "+f"(acc[nt][0]), "+f"(acc[nt][1]),
                      "+f"(acc[nt][2]), "+f"(acc[nt][3])
                    : "r"(a[0]), "r"(a[1]), "r"(a[2]), "r"(a[3]),
                      "r"(b0), "r"(b1v));
            }
        }
    }

    const float* bias = (const float*)(sm + BIAS_OFF);
    const int px_a = px0 + warp*16 + g_;
#pragma unroll
    for (int nt = 0; nt < 8; nt++) {
        int n = nt*8 + tig*2;
        float bx = bias[n], by = bias[n+1];
        float* p0 = g_comp + ((size_t)b*HW_ + px_a) * COMP_ + n;
        *(float2*)p0             = make_float2(acc[nt][0] + bx, acc[nt][1] + by);
        *(float2*)(p0 + 8*COMP_) = make_float2(acc[nt][2] + bx, acc[nt][3] + by);
    }
}

// ================= Kernel B: 3x3 stride-2 conv + fused softmax (f32x2 output pairs) =================
#define CS_ROW   130
#define CS_CH    (5*CS_ROW)
#define NPAIR    13
#define WP_OFF   (COMP_*CS_CH)
#define B_SMEM_BYTES (WP_OFF*4 + NPAIR*COMP_*9*8)

__global__ __launch_bounds__(256) void k_conv2(const float* __restrict__ w2,
                                               const float* __restrict__ b2) {
    extern __shared__ __align__(16) float smemB[];
    float*  cs = smemB;
    float2* wP = (float2*)(smemB + WP_OFF);
    float*  ls = smemB;

    const int b   = blockIdx.y;
    const int hop = blockIdx.x;
    const int tid = threadIdx.x;

    for (int idx = tid; idx < NPAIR*COMP_*9; idx += 256) {
        int p   = idx / (COMP_*9);
        int rem = idx - p*(COMP_*9);
        int o0 = 2*p, o1 = 2*p + 1;
        float wlo = w2[o0*(COMP_*9) + rem];
        float whi = (o1 < KK_) ? w2[o1*(COMP_*9) + rem] : 0.f;
        wP[idx] = make_float2(wlo, whi);
    }

    const int r0 = 4*hop - 1;
#pragma unroll
    for (int r = 0; r < 5; r++) {
        int gr = r0 + r;
        if ((unsigned)gr < (unsigned)H_) {
            const float* src = g_comp + ((size_t)b*HW_ + (size_t)gr*W_) * COMP_;
#pragma unroll 4
            for (int i = tid; i < 128*64; i += 256) {
                int col = (i >> 6) + 1;
                int c   = i & 63;
                cs[c*CS_CH + r*CS_ROW + col] = src[(size_t)(col-1)*COMP_ + c];
            }
            if (tid < 128) {
                int c = tid & 63, side = tid >> 6;
                cs[c*CS_CH + r*CS_ROW + side*129] = 0.f;
            }
        } else {
            for (int i = tid; i < 130*64; i += 256) {
                int col = i >> 6, c = i & 63;
                cs[c*CS_CH + r*CS_ROW + col] = 0.f;
            }
        }
    }
    __syncthreads();

    const int wo = tid & 63;
    const int og = tid >> 6;
    const int nP = (og == 0) ? 4 : 3;

    unsigned long long accP[4][2];
#pragma unroll
    for (int t = 0; t < 4; t++) { accP[t][0] = 0ull; accP[t][1] = 0ull; }

#pragma unroll 1
    for (int c = 0; c < COMP_; c++) {
        const float* csp = cs + c*CS_CH + 2*wo;
        float xv[5][3];
#pragma unroll
        for (int r = 0; r < 5; r++) {
            float2 u = *(const float2*)(csp + r*CS_ROW);
            xv[r][0] = u.x; xv[r][1] = u.y;
            xv[r][2] = csp[r*CS_ROW + 2];
        }
        unsigned long long xd[5][3];
#pragma unroll
        for (int r = 0; r < 5; r++)
#pragma unroll
            for (int j = 0; j < 3; j++) xd[r][j] = dup2(xv[r][j]);

#pragma unroll
        for (int t = 0; t < 4; t++) {
            if (t < nP) {
                int p = og + 4*t;
                const unsigned long long* wpc =
                    (const unsigned long long*)(wP + (p*COMP_ + c)*9);
#pragma unroll
                for (int ki = 0; ki < 3; ki++)
#pragma unroll
                    for (int kj = 0; kj < 3; kj++) {
                        unsigned long long w = wpc[ki*3 + kj];
                        fma2(accP[t][0], w, xd[ki][kj]);
                        fma2(accP[t][1], w, xd[ki+2][kj]);
                    }
            }
        }
    }

    __syncthreads();
#pragma unroll
    for (int t = 0; t < 4; t++) {
        if (t < nP) {
            int p = og + 4*t;
            int o0 = 2*p, o1 = 2*p + 1;
            float2 a0 = unpack2(accP[t][0]);
            float2 a1 = unpack2(accP[t][1]);
            float bz0 = b2[o0];
            ls[(     wo)*29 + o0] = a0.x + bz0;
            ls[(64 + wo)*29 + o0] = a1.x + bz0;
            if (o1 < KK_) {
                float bz1 = b2[o1];
                ls[(     wo)*29 + o1] = a0.y + bz1;
                ls[(64 + wo)*29 + o1] = a1.y + bz1;
            }
        }
    }
    __syncthreads();

    const int ho0 = 2*hop;
    if (tid < 128) {
        const float* lp = ls + tid*29;
        float mx = -1e30f;
#pragma unroll
        for (int o = 0; o < KK_; o++) mx = fmaxf(mx, lp[o]);
        float e[KK_]; float s = 0.f;
#pragma unroll
        for (int o = 0; o < KK_; o++) { e[o] = __expf(lp[o] - mx); s += e[o]; }
        float inv = 1.f / s;
        int ho = ho0 + (tid >> 6);
        int wx = tid & 63;
#pragma unroll
        for (int o = 0; o < KK_; o++)
            g_mask[(((size_t)b*KK_ + o)*HO_ + ho)*WO_ + wx] = e[o] * inv;
    }
}

// ================= Kernel C: CARAFE gather — pair f32x2 + shuffle, lean regs =================
// Thread = (pair p, slot of 8 channels). Per row: ONE float4 (cols 4p..4p+3) +
// ONE float (4p+4); left pair (4p-2,4p-1) comes from lane p-1 via shfl.
// Weights: LDS64 pairs (adjacent in ms). Pipelined with rotate (R9 style).
__global__ __launch_bounds__(256) void k_carafe(const float* __restrict__ x,
                                                float* __restrict__ out) {
    __shared__ __align__(16) float ms[KK_*64];

    const int ho = blockIdx.x;
    const int cq = blockIdx.y;
    const int b  = blockIdx.z;
    const int tid = threadIdx.x;

    for (int idx = tid; idx < KK_*64; idx += 256)
        ms[idx] = g_mask[(((size_t)b*KK_ + (idx >> 6))*HO_ + ho)*WO_ + (idx & 63)];
    __syncthreads();

    const int p    = tid & 31;    // output pair: wo = 2p, 2p+1
    const int slot = tid >> 5;
    const unsigned long long* wp = (const unsigned long long*)(ms + 2*p);

    const int r0 = 2*ho - 2;
    const bool okL = (p > 0);
    const bool okR = (p < 31);
    const float4 z4 = make_float4(0.f, 0.f, 0.f, 0.f);

    bool rok[5];
#pragma unroll
    for (int i = 0; i < 5; i++) { int r = r0 + i; rok[i] = ((unsigned)r < (unsigned)H_); }

    const int c0 = cq*64 + slot*8;
    const float* xc = x + ((size_t)(b*C_ + c0)) * HW_ + 4*p;    // col 4p (16B aligned)
    float* ob = out + (((size_t)(b*C_ + c0))*HO_ + ho)*WO_ + 2*p;

    float4 aq[5]; float af[5];
#pragma unroll
    for (int i = 0; i < 5; i++) {
        const float* base = xc + (size_t)(r0 + i) * W_;
        aq[i] =  rok[i]         ? __ldg((const float4*)base) : z4;
        af[i] = (rok[i] && okR) ? __ldg(base + 4)            : 0.f;
    }

#pragma unroll 1
    for (int t = 0; t < 8; t++) {
        // issue loads for channel t+1 first
        const float* xn = xc + (t < 7 ? HW_ : 0);
        float4 bq[5]; float bf[5];
#pragma unroll
        for (int i = 0; i < 5; i++) {
            const float* base = xn + (size_t)(r0 + i) * W_;
            bq[i] =  rok[i]         ? __ldg((const float4*)base) : z4;
            bf[i] = (rok[i] && okR) ? __ldg(base + 4)            : 0.f;
        }

        unsigned long long acc = 0ull;
#pragma unroll
        for (int i = 0; i < 5; i++) {
            float4 q = aq[i]; float f = af[i];
            float v0 = __shfl_up_sync(0xffffffffu, q.z, 1);   // lane p-1's col 4p-2
            float v1 = __shfl_up_sync(0xffffffffu, q.w, 1);   // lane p-1's col 4p-1
            if (!okL) { v0 = 0.f; v1 = 0.f; }
            fma2(acc, wp[(5*i+0)*32], pack2(v0,  q.x));
            fma2(acc, wp[(5*i+1)*32], pack2(v1,  q.y));
            fma2(acc, wp[(5*i+2)*32], pack2(q.x, q.z));
            fma2(acc, wp[(5*i+3)*32], pack2(q.y, q.w));
            fma2(acc, wp[(5*i+4)*32], pack2(q.z, f));
        }
        float2 o2 = unpack2(acc);
        *(float2*)(ob + (size_t)t * HO_*WO_) = o2;            // coalesced

#pragma unroll
        for (int i = 0; i < 5; i++) { aq[i] = bq[i]; af[i] = bf[i]; }
        xc += HW_;
    }
}

// ================= launch =================
extern "C" void kernel_launch(void* const* d_in, const int* in_sizes, int n_in,
                              void* d_out, int out_size) {
    const float* x  = (const float*)d_in[0];
    const float* w1 = (const float*)d_in[1];
    const float* b1 = (const float*)d_in[2];
    const float* w2 = (const float*)d_in[3];
    const float* b2 = (const float*)d_in[4];
    float* out = (float*)d_out;

    cudaFuncSetAttribute(k_conv1, cudaFuncAttributeMaxDynamicSharedMemorySize, A_SMEM_BYTES);
    cudaFuncSetAttribute(k_conv2, cudaFuncAttributeMaxDynamicSharedMemorySize, B_SMEM_BYTES);

    k_prep<<<64, 256>>>(w1);
    k_conv1<<<dim3(256, 4), 128, A_SMEM_BYTES>>>(x, b1);
    k_conv2<<<dim3(32, 4), 256, B_SMEM_BYTES>>>(w2, b2);
    k_carafe<<<dim3(64, 4, 4), 256>>>(x, out);
}

// round 16
// speedup vs baseline: 1.3434x; 1.0151x over previous
#include <cuda_runtime.h>
#include <cuda_bf16.h>
#include <cstdint>

#define B_    4
#define C_    256
#define H_    128
#define W_    128
#define HW_   (H_*W_)
#define COMP_ 64
#define KK_   25
#define HO_   64
#define WO_   64

// Scratch (device globals; allocation is forbidden)
__device__ float g_comp[B_*HW_*COMP_];     // [b][px][ch] channel-minor
__device__ float g_mask[B_*KK_*HO_*WO_];   // NORMALIZED softmax weights
__device__ __align__(16) unsigned char g_w1b[COMP_*C_*2];   // w1 bf16 PRE-SWIZZLED

__device__ __forceinline__ uint32_t smem_u32(const void* p) {
    uint32_t a;
    asm("{ .reg .u64 t; cvta.to.shared.u64 t, %1; cvt.u32.u64 %0, t; }" : "=r"(a) : "l"(p));
    return a;
}
__device__ __forceinline__ unsigned long long pack2(float lo, float hi) {
    unsigned long long r;
    asm("mov.b64 %0, {%1, %2};" : "=l"(r)
        : "r"(__float_as_uint(lo)), "r"(__float_as_uint(hi)));
    return r;
}
__device__ __forceinline__ unsigned long long dup2(float w) {
    unsigned long long r;
    asm("mov.b64 %0, {%1, %1};" : "=l"(r) : "r"(__float_as_uint(w)));
    return r;
}
__device__ __forceinline__ void fma2(unsigned long long& d,
                                     unsigned long long a, unsigned long long b) {
    asm("fma.rn.f32x2 %0, %1, %2, %0;" : "+l"(d) : "l"(a), "l"(b));
}
__device__ __forceinline__ float2 unpack2(unsigned long long v) {
    unsigned lo, hi;
    asm("mov.b64 {%0, %1}, %2;" : "=r"(lo), "=r"(hi) : "l"(v));
    return make_float2(__uint_as_float(lo), __uint_as_float(hi));
}
__device__ __forceinline__ void cp_async16(uint32_t dst, const void* src) {
    asm volatile("{ .reg .u64 g; cvta.to.global.u64 g, %1; "
                 "cp.async.cg.shared.global [%0], [g], 16; }"
                 :: "r"(dst), "l"(src));
}

// ================= Kernel P: w1 fp32 -> bf16, PRE-SWIZZLED =================
__global__ void k_prep(const float* __restrict__ w1) {
    int idx = blockIdx.x * 256 + threadIdx.x;      // n*256 + k
    if (idx < COMP_ * C_) {
        int n = idx >> 8, k = idx & 255;
        int cx = k >> 3;
        uint32_t off = (uint32_t)(n*512 + ((cx ^ (n & 7)) << 4) + (k & 7)*2);
        *(__nv_bfloat16*)(g_w1b + off) = __float2bfloat16(w1[idx]);
    }
}

// ================= Kernel A: 1x1 conv via mma.sync bf16 (64-px tiles) =================
#define XS_OFF   0
#define WS_OFF   8192
#define BIAS_OFF (8192 + 32768)
#define A_SMEM_BYTES (BIAS_OFF + 256)

__global__ __launch_bounds__(128) void k_conv1(const float* __restrict__ x,
                                               const float* __restrict__ b1) {
    extern __shared__ __align__(16) char sm[];
    const uint32_t smb = smem_u32(sm);
    const int tid  = threadIdx.x;
    const int warp = tid >> 5;
    const int lane = tid & 31;
    const int b    = blockIdx.y;
    const int px0  = blockIdx.x * 64;

#pragma unroll
    for (int l = 0; l < 16; l++) {
        int i = l*128 + tid;
        cp_async16(smb + WS_OFF + (uint32_t)i*16, (const char*)g_w1b + (size_t)i*16);
    }
    asm volatile("cp.async.commit_group;" ::: "memory");
    if (tid < 64) ((float*)(sm + BIAS_OFF))[tid] = b1[tid];

    float acc[8][4];
#pragma unroll
    for (int nt = 0; nt < 8; nt++)
#pragma unroll
        for (int i = 0; i < 4; i++) acc[nt][i] = 0.f;

    const int lj  = lane & 7;
    const int lg2 = (lane >> 3) & 1;
    const int lg4 = lane >> 4;
    const int g_  = lane >> 2;
    const int tig = lane & 3;

    const float* xbase = x + ((size_t)b * C_) * HW_ + px0;

    for (int chunk = 0; chunk < 4; chunk++) {
        __syncthreads();
        const float4* xsrc = (const float4*)(xbase + (size_t)(chunk * 64) * HW_);
#pragma unroll
        for (int l = 0; l < 8; l++) {
            int id = l*128 + tid;
            int ch = id >> 4, f4 = id & 15;
            float4 v = xsrc[(size_t)ch * (HW_/4) + f4];
            __nv_bfloat162 h0 = __float22bfloat162_rn(make_float2(v.x, v.y));
            __nv_bfloat162 h1 = __float22bfloat162_rn(make_float2(v.z, v.w));
            int cx = f4 >> 1;
            uint32_t off = XS_OFF + ch*128 + (uint32_t)((cx ^ (ch & 7)) << 4) + (f4 & 1) * 8;
            *(uint2*)(sm + off) = make_uint2(*(uint32_t*)&h0, *(uint32_t*)&h1);
        }
        if (chunk == 0)
            asm volatile("cp.async.wait_group 0;" ::: "memory");
        __syncthreads();

#pragma unroll
        for (int s = 0; s < 4; s++) {
            uint32_t a[4];
            const int krow  = s*16 + lj + lg4*8;
            const int pxcol = warp*16 + lg2*8;
            uint32_t addr = smb + XS_OFF + krow*128
                          + (uint32_t)(((pxcol >> 3) ^ (krow & 7)) << 4);
            asm volatile("ldmatrix.sync.aligned.m8n8.x4.trans.shared.b16 "
                         "{%0,%1,%2,%3}, [%4];"
                         : "=r"(a[0]), "=r"(a[1]), "=r"(a[2]), "=r"(a[3])
                         : "r"(addr));
            const int kabs = chunk*64 + s*16;
            const int cx0  = kabs >> 3;
#pragma unroll
            for (int nt = 0; nt < 8; nt++) {
                int n = nt*8 + g_;
                uint32_t ab0 = smb + WS_OFF + n*512
                             + (uint32_t)(((cx0     ) ^ (n & 7)) << 4) + tig*4;
                uint32_t ab1 = smb + WS_OFF + n*512
                             + (uint32_t)(((cx0 + 1) ^ (n & 7)) << 4) + tig*4;
                uint32_t b0, b1v;
                asm volatile("ld.shared.b32 %0, [%1];" : "=r"(b0)  : "r"(ab0));
                asm volatile("ld.shared.b32 %0, [%1];" : "=r"(b1v) : "r"(ab1));
                asm volatile(
                    "mma.sync.aligned.m16n8k16.row.col.f32.bf16.bf16.f32 "
                    "{%0,%1,%2,%3}, {%4,%5,%6,%7}, {%8,%9}, {%0,%1,%2,%3};"
                    : "+f"(acc[nt][0]), "+f"(acc[nt][1]),
                      "+f"(acc[nt][2]), "+f"(acc[nt][3])
                    : "r"(a[0]), "r"(a[1]), "r"(a[2]), "r"(a[3]),
                      "r"(b0), "r"(b1v));
            }
        }
    }

    const float* bias = (const float*)(sm + BIAS_OFF);
    const int px_a = px0 + warp*16 + g_;
#pragma unroll
    for (int nt = 0; nt < 8; nt++) {
        int n = nt*8 + tig*2;
        float bx = bias[n], by = bias[n+1];
        float* p0 = g_comp + ((size_t)b*HW_ + px_a) * COMP_ + n;
        *(float2*)p0             = make_float2(acc[nt][0] + bx, acc[nt][1] + by);
        *(float2*)(p0 + 8*COMP_) = make_float2(acc[nt][2] + bx, acc[nt][3] + by);
    }
}

// ================= Kernel B: 3x3 stride-2 conv + fused softmax (f32x2 output pairs) =================
#define CS_ROW   130
#define CS_CH    (5*CS_ROW)
#define NPAIR    13
#define WP_OFF   (COMP_*CS_CH)
#define B_SMEM_BYTES (WP_OFF*4 + NPAIR*COMP_*9*8)

__global__ __launch_bounds__(256) void k_conv2(const float* __restrict__ w2,
                                               const float* __restrict__ b2) {
    extern __shared__ __align__(16) float smemB[];
    float*  cs = smemB;
    float2* wP = (float2*)(smemB + WP_OFF);
    float*  ls = smemB;

    const int b   = blockIdx.y;
    const int hop = blockIdx.x;
    const int tid = threadIdx.x;

    for (int idx = tid; idx < NPAIR*COMP_*9; idx += 256) {
        int p   = idx / (COMP_*9);
        int rem = idx - p*(COMP_*9);
        int o0 = 2*p, o1 = 2*p + 1;
        float wlo = w2[o0*(COMP_*9) + rem];
        float whi = (o1 < KK_) ? w2[o1*(COMP_*9) + rem] : 0.f;
        wP[idx] = make_float2(wlo, whi);
    }

    const int r0 = 4*hop - 1;
#pragma unroll
    for (int r = 0; r < 5; r++) {
        int gr = r0 + r;
        if ((unsigned)gr < (unsigned)H_) {
            const float* src = g_comp + ((size_t)b*HW_ + (size_t)gr*W_) * COMP_;
#pragma unroll 4
            for (int i = tid; i < 128*64; i += 256) {
                int col = (i >> 6) + 1;
                int c   = i & 63;
                cs[c*CS_CH + r*CS_ROW + col] = src[(size_t)(col-1)*COMP_ + c];
            }
            if (tid < 128) {
                int c = tid & 63, side = tid >> 6;
                cs[c*CS_CH + r*CS_ROW + side*129] = 0.f;
            }
        } else {
            for (int i = tid; i < 130*64; i += 256) {
                int col = i >> 6, c = i & 63;
                cs[c*CS_CH + r*CS_ROW + col] = 0.f;
            }
        }
    }
    __syncthreads();

    const int wo = tid & 63;
    const int og = tid >> 6;
    const int nP = (og == 0) ? 4 : 3;

    unsigned long long accP[4][2];
#pragma unroll
    for (int t = 0; t < 4; t++) { accP[t][0] = 0ull; accP[t][1] = 0ull; }

#pragma unroll 1
    for (int c = 0; c < COMP_; c++) {
        const float* csp = cs + c*CS_CH + 2*wo;
        float xv[5][3];
#pragma unroll
        for (int r = 0; r < 5; r++) {
            float2 u = *(const float2*)(csp + r*CS_ROW);
            xv[r][0] = u.x; xv[r][1] = u.y;
            xv[r][2] = csp[r*CS_ROW + 2];
        }
        unsigned long long xd[5][3];
#pragma unroll
        for (int r = 0; r < 5; r++)
#pragma unroll
            for (int j = 0; j < 3; j++) xd[r][j] = dup2(xv[r][j]);

#pragma unroll
        for (int t = 0; t < 4; t++) {
            if (t < nP) {
                int p = og + 4*t;
                const unsigned long long* wpc =
                    (const unsigned long long*)(wP + (p*COMP_ + c)*9);
#pragma unroll
                for (int ki = 0; ki < 3; ki++)
#pragma unroll
                    for (int kj = 0; kj < 3; kj++) {
                        unsigned long long w = wpc[ki*3 + kj];
                        fma2(accP[t][0], w, xd[ki][kj]);
                        fma2(accP[t][1], w, xd[ki+2][kj]);
                    }
            }
        }
    }

    __syncthreads();
#pragma unroll
    for (int t = 0; t < 4; t++) {
        if (t < nP) {
            int p = og + 4*t;
            int o0 = 2*p, o1 = 2*p + 1;
            float2 a0 = unpack2(accP[t][0]);
            float2 a1 = unpack2(accP[t][1]);
            float bz0 = b2[o0];
            ls[(     wo)*29 + o0] = a0.x + bz0;
            ls[(64 + wo)*29 + o0] = a1.x + bz0;
            if (o1 < KK_) {
                float bz1 = b2[o1];
                ls[(     wo)*29 + o1] = a0.y + bz1;
                ls[(64 + wo)*29 + o1] = a1.y + bz1;
            }
        }
    }
    __syncthreads();

    const int ho0 = 2*hop;
    if (tid < 128) {
        const float* lp = ls + tid*29;
        float mx = -1e30f;
#pragma unroll
        for (int o = 0; o < KK_; o++) mx = fmaxf(mx, lp[o]);
        float e[KK_]; float s = 0.f;
#pragma unroll
        for (int o = 0; o < KK_; o++) { e[o] = __expf(lp[o] - mx); s += e[o]; }
        float inv = 1.f / s;
        int ho = ho0 + (tid >> 6);
        int wx = tid & 63;
#pragma unroll
        for (int o = 0; o < KK_; o++)
            g_mask[(((size_t)b*KK_ + o)*HO_ + ho)*WO_ + wx] = e[o] * inv;
    }
}

// ================= Kernel C: CARAFE gather — pair f32x2, all-shuffle halo =================
// Thread = (pair p, slot of 8 channels). Per row ONE float4 (cols 4p..4p+3);
// left pair (4p-2,4p-1) = lane p-1's (q.z,q.w) via shfl_up; right scalar
// (4p+4) = lane p+1's q.x via shfl_down. Weights via LDS64 pairs. Pipelined.
__global__ __launch_bounds__(256, 4) void k_carafe(const float* __restrict__ x,
                                                   float* __restrict__ out) {
    __shared__ __align__(16) float ms[KK_*64];

    const int ho = blockIdx.x;
    const int cq = blockIdx.y;
    const int b  = blockIdx.z;
    const int tid = threadIdx.x;

    for (int idx = tid; idx < KK_*64; idx += 256)
        ms[idx] = g_mask[(((size_t)b*KK_ + (idx >> 6))*HO_ + ho)*WO_ + (idx & 63)];
    __syncthreads();

    const int p    = tid & 31;    // output pair: wo = 2p, 2p+1
    const int slot = tid >> 5;
    const unsigned long long* wp = (const unsigned long long*)(ms + 2*p);

    const int r0 = 2*ho - 2;
    const bool okL = (p > 0);
    const bool okR = (p < 31);
    const float4 z4 = make_float4(0.f, 0.f, 0.f, 0.f);

    bool rok[5];
#pragma unroll
    for (int i = 0; i < 5; i++) { int r = r0 + i; rok[i] = ((unsigned)r < (unsigned)H_); }

    const int c0 = cq*64 + slot*8;
    const float* xc = x + ((size_t)(b*C_ + c0)) * HW_ + 4*p;    // col 4p (16B aligned)
    float* ob = out + (((size_t)(b*C_ + c0))*HO_ + ho)*WO_ + 2*p;

    float4 aq[5];
#pragma unroll
    for (int i = 0; i < 5; i++) {
        const float* base = xc + (size_t)(r0 + i) * W_;
        aq[i] = rok[i] ? __ldg((const float4*)base) : z4;
    }

#pragma unroll 1
    for (int t = 0; t < 8; t++) {
        // issue loads for channel t+1 first (overlap with FMAs below)
        const float* xn = xc + (t < 7 ? HW_ : 0);
        float4 bq[5];
#pragma unroll
        for (int i = 0; i < 5; i++) {
            const float* base = xn + (size_t)(r0 + i) * W_;
            bq[i] = rok[i] ? __ldg((const float4*)base) : z4;
        }

        unsigned long long acc = 0ull;
#pragma unroll
        for (int i = 0; i < 5; i++) {
            float4 q = aq[i];
            float v0 = __shfl_up_sync(0xffffffffu, q.z, 1);    // lane p-1: col 4p-2
            float v1 = __shfl_up_sync(0xffffffffu, q.w, 1);    // lane p-1: col 4p-1
            float f  = __shfl_down_sync(0xffffffffu, q.x, 1);  // lane p+1: col 4p+4
            if (!okL) { v0 = 0.f; v1 = 0.f; }
            if (!okR) { f = 0.f; }
            fma2(acc, wp[(5*i+0)*32], pack2(v0,  q.x));
            fma2(acc, wp[(5*i+1)*32], pack2(v1,  q.y));
            fma2(acc, wp[(5*i+2)*32], pack2(q.x, q.z));
            fma2(acc, wp[(5*i+3)*32], pack2(q.y, q.w));
            fma2(acc, wp[(5*i+4)*32], pack2(q.z, f));
        }
        float2 o2 = unpack2(acc);
        *(float2*)(ob + (size_t)t * HO_*WO_) = o2;             // coalesced

#pragma unroll
        for (int i = 0; i < 5; i++) aq[i] = bq[i];
        xc += HW_;
    }
}

// ================= launch =================
extern "C" void kernel_launch(void* const* d_in, const int* in_sizes, int n_in,
                              void* d_out, int out_size) {
    const float* x  = (const float*)d_in[0];
    const float* w1 = (const float*)d_in[1];
    const float* b1 = (const float*)d_in[2];
    const float* w2 = (const float*)d_in[3];
    const float* b2 = (const float*)d_in[4];
    float* out = (float*)d_out;

    cudaFuncSetAttribute(k_conv1, cudaFuncAttributeMaxDynamicSharedMemorySize, A_SMEM_BYTES);
    cudaFuncSetAttribute(k_conv2, cudaFuncAttributeMaxDynamicSharedMemorySize, B_SMEM_BYTES);

    k_prep<<<64, 256>>>(w1);
    k_conv1<<<dim3(256, 4), 128, A_SMEM_BYTES>>>(x, b1);
    k_conv2<<<dim3(32, 4), 256, B_SMEM_BYTES>>>(w2, b2);
    k_carafe<<<dim3(64, 4, 4), 256>>>(x, out);
}

// round 17
// speedup vs baseline: 1.5456x; 1.1505x over previous
#include <cuda_runtime.h>
#include <cuda_bf16.h>
#include <cstdint>

#define B_    4
#define C_    256
#define H_    128
#define W_    128
#define HW_   (H_*W_)
#define COMP_ 64
#define KK_   25
#define HO_   64
#define WO_   64

// Scratch (device globals; allocation is forbidden)
__device__ float g_comp[B_*HW_*COMP_];     // [b][px][ch] channel-minor
__device__ float g_mask[B_*KK_*HO_*WO_];   // NORMALIZED softmax weights
__device__ __align__(16) unsigned char g_w1b[COMP_*C_*2];   // w1 bf16 PRE-SWIZZLED

__device__ __forceinline__ uint32_t smem_u32(const void* p) {
    uint32_t a;
    asm("{ .reg .u64 t; cvta.to.shared.u64 t, %1; cvt.u32.u64 %0, t; }" : "=r"(a) : "l"(p));
    return a;
}
__device__ __forceinline__ unsigned long long pack2(float lo, float hi) {
    unsigned long long r;
    asm("mov.b64 %0, {%1, %2};" : "=l"(r)
        : "r"(__float_as_uint(lo)), "r"(__float_as_uint(hi)));
    return r;
}
__device__ __forceinline__ unsigned long long dup2(float w) {
    unsigned long long r;
    asm("mov.b64 %0, {%1, %1};" : "=l"(r) : "r"(__float_as_uint(w)));
    return r;
}
__device__ __forceinline__ void fma2(unsigned long long& d,
                                     unsigned long long a, unsigned long long b) {
    asm("fma.rn.f32x2 %0, %1, %2, %0;" : "+l"(d) : "l"(a), "l"(b));
}
__device__ __forceinline__ float2 unpack2(unsigned long long v) {
    unsigned lo, hi;
    asm("mov.b64 {%0, %1}, %2;" : "=r"(lo), "=r"(hi) : "l"(v));
    return make_float2(__uint_as_float(lo), __uint_as_float(hi));
}
__device__ __forceinline__ void cp_async16(uint32_t dst, const void* src) {
    asm volatile("{ .reg .u64 g; cvta.to.global.u64 g, %1; "
                 "cp.async.cg.shared.global [%0], [g], 16; }"
                 :: "r"(dst), "l"(src));
}

// ================= Kernel P: w1 fp32 -> bf16, PRE-SWIZZLED =================
__global__ void k_prep(const float* __restrict__ w1) {
    int idx = blockIdx.x * 256 + threadIdx.x;      // n*256 + k
    if (idx < COMP_ * C_) {
        int n = idx >> 8, k = idx & 255;
        int cx = k >> 3;
        uint32_t off = (uint32_t)(n*512 + ((cx ^ (n & 7)) << 4) + (k & 7)*2);
        *(__nv_bfloat16*)(g_w1b + off) = __float2bfloat16(w1[idx]);
    }
}

// ================= Kernel A: 1x1 conv via mma.sync bf16 (64-px tiles) =================
#define XS_OFF   0
#define WS_OFF   8192
#define BIAS_OFF (8192 + 32768)
#define A_SMEM_BYTES (BIAS_OFF + 256)

__global__ __launch_bounds__(128) void k_conv1(const float* __restrict__ x,
                                               const float* __restrict__ b1) {
    extern __shared__ __align__(16) char sm[];
    const uint32_t smb = smem_u32(sm);
    const int tid  = threadIdx.x;
    const int warp = tid >> 5;
    const int lane = tid & 31;
    const int b    = blockIdx.y;
    const int px0  = blockIdx.x * 64;

#pragma unroll
    for (int l = 0; l < 16; l++) {
        int i = l*128 + tid;
        cp_async16(smb + WS_OFF + (uint32_t)i*16, (const char*)g_w1b + (size_t)i*16);
    }
    asm volatile("cp.async.commit_group;" ::: "memory");
    if (tid < 64) ((float*)(sm + BIAS_OFF))[tid] = b1[tid];

    float acc[8][4];
#pragma unroll
    for (int nt = 0; nt < 8; nt++)
#pragma unroll
        for (int i = 0; i < 4; i++) acc[nt][i] = 0.f;

    const int lj  = lane & 7;
    const int lg2 = (lane >> 3) & 1;
    const int lg4 = lane >> 4;
    const int g_  = lane >> 2;
    const int tig = lane & 3;

    const float* xbase = x + ((size_t)b * C_) * HW_ + px0;

    for (int chunk = 0; chunk < 4; chunk++) {
        __syncthreads();
        const float4* xsrc = (const float4*)(xbase + (size_t)(chunk * 64) * HW_);
#pragma unroll
        for (int l = 0; l < 8; l++) {
            int id = l*128 + tid;
            int ch = id >> 4, f4 = id & 15;
            float4 v = xsrc[(size_t)ch * (HW_/4) + f4];
            __nv_bfloat162 h0 = __float22bfloat162_rn(make_float2(v.x, v.y));
            __nv_bfloat162 h1 = __float22bfloat162_rn(make_float2(v.z, v.w));
            int cx = f4 >> 1;
            uint32_t off = XS_OFF + ch*128 + (uint32_t)((cx ^ (ch & 7)) << 4) + (f4 & 1) * 8;
            *(uint2*)(sm + off) = make_uint2(*(uint32_t*)&h0, *(uint32_t*)&h1);
        }
        if (chunk == 0)
            asm volatile("cp.async.wait_group 0;" ::: "memory");
        __syncthreads();

#pragma unroll
        for (int s = 0; s < 4; s++) {
            uint32_t a[4];
            const int krow  = s*16 + lj + lg4*8;
            const int pxcol = warp*16 + lg2*8;
            uint32_t addr = smb + XS_OFF + krow*128
                          + (uint32_t)(((pxcol >> 3) ^ (krow & 7)) << 4);
            asm volatile("ldmatrix.sync.aligned.m8n8.x4.trans.shared.b16 "
                         "{%0,%1,%2,%3}, [%4];"
                         : "=r"(a[0]), "=r"(a[1]), "=r"(a[2]), "=r"(a[3])
                         : "r"(addr));
            const int kabs = chunk*64 + s*16;
            const int cx0  = kabs >> 3;
#pragma unroll
            for (int nt = 0; nt < 8; nt++) {
                int n = nt*8 + g_;
                uint32_t ab0 = smb + WS_OFF + n*512
                             + (uint32_t)(((cx0     ) ^ (n & 7)) << 4) + tig*4;
                uint32_t ab1 = smb + WS_OFF + n*512
                             + (uint32_t)(((cx0 + 1) ^ (n & 7)) << 4) + tig*4;
                uint32_t b0, b1v;
                asm volatile("ld.shared.b32 %0, [%1];" : "=r"(b0)  : "r"(ab0));
                asm volatile("ld.shared.b32 %0, [%1];" : "=r"(b1v) : "r"(ab1));
                asm volatile(
                    "mma.sync.aligned.m16n8k16.row.col.f32.bf16.bf16.f32 "
                    "{%0,%1,%2,%3}, {%4,%5,%6,%7}, {%8,%9}, {%0,%1,%2,%3};"
                    : "+f"(acc[nt][0]), "+f"(acc[nt][1]),
                      "+f"(acc[nt][2]), "+f"(acc[nt][3])
                    : "r"(a[0]), "r"(a[1]), "r"(a[2]), "r"(a[3]),
                      "r"(b0), "r"(b1v));
            }
        }
    }

    const float* bias = (const float*)(sm + BIAS_OFF);
    const int px_a = px0 + warp*16 + g_;
#pragma unroll
    for (int nt = 0; nt < 8; nt++) {
        int n = nt*8 + tig*2;
        float bx = bias[n], by = bias[n+1];
        float* p0 = g_comp + ((size_t)b*HW_ + px_a) * COMP_ + n;
        *(float2*)p0             = make_float2(acc[nt][0] + bx, acc[nt][1] + by);
        *(float2*)(p0 + 8*COMP_) = make_float2(acc[nt][2] + bx, acc[nt][3] + by);
    }
}

// ================= Kernel B: 3x3 stride-2 conv + fused softmax (f32x2 output pairs) =================
#define CS_ROW   130
#define CS_CH    (5*CS_ROW)
#define NPAIR    13
#define WP_OFF   (COMP_*CS_CH)
#define B_SMEM_BYTES (WP_OFF*4 + NPAIR*COMP_*9*8)

__global__ __launch_bounds__(256) void k_conv2(const float* __restrict__ w2,
                                               const float* __restrict__ b2) {
    extern __shared__ __align__(16) float smemB[];
    float*  cs = smemB;
    float2* wP = (float2*)(smemB + WP_OFF);
    float*  ls = smemB;

    const int b   = blockIdx.y;
    const int hop = blockIdx.x;
    const int tid = threadIdx.x;

    for (int idx = tid; idx < NPAIR*COMP_*9; idx += 256) {
        int p   = idx / (COMP_*9);
        int rem = idx - p*(COMP_*9);
        int o0 = 2*p, o1 = 2*p + 1;
        float wlo = w2[o0*(COMP_*9) + rem];
        float whi = (o1 < KK_) ? w2[o1*(COMP_*9) + rem] : 0.f;
        wP[idx] = make_float2(wlo, whi);
    }

    const int r0 = 4*hop - 1;
#pragma unroll
    for (int r = 0; r < 5; r++) {
        int gr = r0 + r;
        if ((unsigned)gr < (unsigned)H_) {
            const float* src = g_comp + ((size_t)b*HW_ + (size_t)gr*W_) * COMP_;
#pragma unroll 4
            for (int i = tid; i < 128*64; i += 256) {
                int col = (i >> 6) + 1;
                int c   = i & 63;
                cs[c*CS_CH + r*CS_ROW + col] = src[(size_t)(col-1)*COMP_ + c];
            }
            if (tid < 128) {
                int c = tid & 63, side = tid >> 6;
                cs[c*CS_CH + r*CS_ROW + side*129] = 0.f;
            }
        } else {
            for (int i = tid; i < 130*64; i += 256) {
                int col = i >> 6, c = i & 63;
                cs[c*CS_CH + r*CS_ROW + col] = 0.f;
            }
        }
    }
    __syncthreads();

    const int wo = tid & 63;
    const int og = tid >> 6;
    const int nP = (og == 0) ? 4 : 3;

    unsigned long long accP[4][2];
#pragma unroll
    for (int t = 0; t < 4; t++) { accP[t][0] = 0ull; accP[t][1] = 0ull; }

#pragma unroll 1
    for (int c = 0; c < COMP_; c++) {
        const float* csp = cs + c*CS_CH + 2*wo;
        float xv[5][3];
#pragma unroll
        for (int r = 0; r < 5; r++) {
            float2 u = *(const float2*)(csp + r*CS_ROW);
            xv[r][0] = u.x; xv[r][1] = u.y;
            xv[r][2] = csp[r*CS_ROW + 2];
        }
        unsigned long long xd[5][3];
#pragma unroll
        for (int r = 0; r < 5; r++)
#pragma unroll
            for (int j = 0; j < 3; j++) xd[r][j] = dup2(xv[r][j]);

#pragma unroll
        for (int t = 0; t < 4; t++) {
            if (t < nP) {
                int p = og + 4*t;
                const unsigned long long* wpc =
                    (const unsigned long long*)(wP + (p*COMP_ + c)*9);
#pragma unroll
                for (int ki = 0; ki < 3; ki++)
#pragma unroll
                    for (int kj = 0; kj < 3; kj++) {
                        unsigned long long w = wpc[ki*3 + kj];
                        fma2(accP[t][0], w, xd[ki][kj]);
                        fma2(accP[t][1], w, xd[ki+2][kj]);
                    }
            }
        }
    }

    __syncthreads();
#pragma unroll
    for (int t = 0; t < 4; t++) {
        if (t < nP) {
            int p = og + 4*t;
            int o0 = 2*p, o1 = 2*p + 1;
            float2 a0 = unpack2(accP[t][0]);
            float2 a1 = unpack2(accP[t][1]);
            float bz0 = b2[o0];
            ls[(     wo)*29 + o0] = a0.x + bz0;
            ls[(64 + wo)*29 + o0] = a1.x + bz0;
            if (o1 < KK_) {
                float bz1 = b2[o1];
                ls[(     wo)*29 + o1] = a0.y + bz1;
                ls[(64 + wo)*29 + o1] = a1.y + bz1;
            }
        }
    }
    __syncthreads();

    const int ho0 = 2*hop;
    if (tid < 128) {
        const float* lp = ls + tid*29;
        float mx = -1e30f;
#pragma unroll
        for (int o = 0; o < KK_; o++) mx = fmaxf(mx, lp[o]);
        float e[KK_]; float s = 0.f;
#pragma unroll
        for (int o = 0; o < KK_; o++) { e[o] = __expf(lp[o] - mx); s += e[o]; }
        float inv = 1.f / s;
        int ho = ho0 + (tid >> 6);
        int wx = tid & 63;
#pragma unroll
        for (int o = 0; o < KK_; o++)
            g_mask[(((size_t)b*KK_ + o)*HO_ + ho)*WO_ + wx] = e[o] * inv;
    }
}

// ================= Kernel C: CARAFE gather — pair f32x2, weight LDS shared over 2 channels =================
// Thread = (pair p, slot of 8 channels). Channels processed two at a time:
// each weight LDS64 feeds BOTH channels' fma2. Halo via shfl (no extra loads).
__global__ __launch_bounds__(256, 4) void k_carafe(const float* __restrict__ x,
                                                   float* __restrict__ out) {
    __shared__ __align__(16) float ms[KK_*64];

    const int ho = blockIdx.x;
    const int cq = blockIdx.y;
    const int b  = blockIdx.z;
    const int tid = threadIdx.x;

    for (int idx = tid; idx < KK_*64; idx += 256)
        ms[idx] = g_mask[(((size_t)b*KK_ + (idx >> 6))*HO_ + ho)*WO_ + (idx & 63)];
    __syncthreads();

    const int p    = tid & 31;    // output pair: wo = 2p, 2p+1
    const int slot = tid >> 5;
    const unsigned long long* wp = (const unsigned long long*)(ms + 2*p);

    const int r0 = 2*ho - 2;
    const bool okL = (p > 0);
    const bool okR = (p < 31);
    const float4 z4 = make_float4(0.f, 0.f, 0.f, 0.f);

    bool rok[5];
#pragma unroll
    for (int i = 0; i < 5; i++) { int r = r0 + i; rok[i] = ((unsigned)r < (unsigned)H_); }

    const int c0 = cq*64 + slot*8;
    const float* xc = x + ((size_t)(b*C_ + c0)) * HW_ + 4*p;    // col 4p (16B aligned)
    float* ob = out + (((size_t)(b*C_ + c0))*HO_ + ho)*WO_ + 2*p;

#pragma unroll 1
    for (int t = 0; t < 4; t++) {                 // channel pair (2t, 2t+1)
        float4 qA[5], qB[5];
#pragma unroll
        for (int i = 0; i < 5; i++)
            qA[i] = rok[i] ? __ldg((const float4*)(xc + (size_t)(r0 + i)*W_)) : z4;
#pragma unroll
        for (int i = 0; i < 5; i++)
            qB[i] = rok[i] ? __ldg((const float4*)(xc + HW_ + (size_t)(r0 + i)*W_)) : z4;

        unsigned long long accA = 0ull, accB = 0ull;
#pragma unroll
        for (int i = 0; i < 5; i++) {
            float4 a = qA[i], bb = qB[i];
            float a0 = __shfl_up_sync(0xffffffffu, a.z, 1);
            float a1 = __shfl_up_sync(0xffffffffu, a.w, 1);
            float afr = __shfl_down_sync(0xffffffffu, a.x, 1);
            float b0 = __shfl_up_sync(0xffffffffu, bb.z, 1);
            float b1 = __shfl_up_sync(0xffffffffu, bb.w, 1);
            float bfr = __shfl_down_sync(0xffffffffu, bb.x, 1);
            if (!okL) { a0 = 0.f; a1 = 0.f; b0 = 0.f; b1 = 0.f; }
            if (!okR) { afr = 0.f; bfr = 0.f; }
            unsigned long long w;
            w = wp[(5*i+0)*32];
            fma2(accA, w, pack2(a0,  a.x));  fma2(accB, w, pack2(b0,  bb.x));
            w = wp[(5*i+1)*32];
            fma2(accA, w, pack2(a1,  a.y));  fma2(accB, w, pack2(b1,  bb.y));
            w = wp[(5*i+2)*32];
            fma2(accA, w, pack2(a.x, a.z));  fma2(accB, w, pack2(bb.x, bb.z));
            w = wp[(5*i+3)*32];
            fma2(accA, w, pack2(a.y, a.w));  fma2(accB, w, pack2(bb.y, bb.w));
            w = wp[(5*i+4)*32];
            fma2(accA, w, pack2(a.z, afr));  fma2(accB, w, pack2(bb.z, bfr));
        }
        float2 oA = unpack2(accA);
        float2 oB = unpack2(accB);
        *(float2*)(ob + (size_t)(2*t    ) * HO_*WO_) = oA;    // coalesced
        *(float2*)(ob + (size_t)(2*t + 1) * HO_*WO_) = oB;
        xc += 2*HW_;
    }
}

// ================= launch =================
extern "C" void kernel_launch(void* const* d_in, const int* in_sizes, int n_in,
                              void* d_out, int out_size) {
    const float* x  = (const float*)d_in[0];
    const float* w1 = (const float*)d_in[1];
    const float* b1 = (const float*)d_in[2];
    const float* w2 = (const float*)d_in[3];
    const float* b2 = (const float*)d_in[4];
    float* out = (float*)d_out;

    cudaFuncSetAttribute(k_conv1, cudaFuncAttributeMaxDynamicSharedMemorySize, A_SMEM_BYTES);
    cudaFuncSetAttribute(k_conv2, cudaFuncAttributeMaxDynamicSharedMemorySize, B_SMEM_BYTES);

    k_prep<<<64, 256>>>(w1);
    k_conv1<<<dim3(256, 4), 128, A_SMEM_BYTES>>>(x, b1);
    k_conv2<<<dim3(32, 4), 256, B_SMEM_BYTES>>>(w2, b2);
    k_carafe<<<dim3(64, 4, 4), 256>>>(x, out);
}